// round 6
// baseline (speedup 1.0000x reference)
#include <cuda_runtime.h>
#include <math.h>
#include <stdint.h>

// Problem dims
#define HH 128
#define WW 128
#define BB 8
#define DD 128
#define MM (HH*WW*BB)          // 131072 rows

typedef unsigned long long ull;

// ---------------- scratch (no cudaMalloc allowed) ----------------
__device__ float  g_inp [MM * 256];   // silu(x@W_in + b_in), interleaved re/im
__device__ float  g_gate[MM * 256];   // silu(x@W_gate + b_gate)
__device__ float  g_lam [MM * 128];   // sigmoid(x@W_lambda + b_lambda)
__device__ float2 g_acc [MM * 128];   // sum of 4 scans

static __device__ __forceinline__ float sigmoidf_(float v) {
    return 1.0f / (1.0f + expf(-v));
}

// ---------------- packed fp32x2 helpers (k4) ----------------
static __device__ __forceinline__ ull pack2(float v) {
    ull r; asm("mov.b64 %0, {%1, %1};" : "=l"(r) : "f"(v)); return r;
}
static __device__ __forceinline__ void ffma2(ull &d, ull a, ull b) {
    asm("fma.rn.f32x2 %0, %1, %2, %0;" : "+l"(d) : "l"(a), "l"(b));
}
static __device__ __forceinline__ void lds2(ull &a, ull &b, unsigned addr) {
    asm volatile("ld.shared.v2.b64 {%0, %1}, [%2];" : "=l"(a), "=l"(b) : "r"(addr));
}
static __device__ __forceinline__ float2 unpack2(ull v) {
    float2 r; asm("mov.b64 {%0, %1}, %2;" : "=f"(r.x), "=f"(r.y) : "l"(v)); return r;
}

// ---------------- tf32 helpers (k1 mma.sync path) ----------------
static __device__ __forceinline__ uint32_t cvt_tf32(float f) {
    uint32_t r; asm("cvt.rna.tf32.f32 %0, %1;" : "=r"(r) : "f"(f)); return r;
}
static __device__ __forceinline__ void mma_tf32(float* c, uint4 a, uint2 b) {
    asm volatile(
        "mma.sync.aligned.m16n8k8.row.col.f32.tf32.tf32.f32 "
        "{%0,%1,%2,%3}, {%4,%5,%6,%7}, {%8,%9}, {%0,%1,%2,%3};"
        : "+f"(c[0]), "+f"(c[1]), "+f"(c[2]), "+f"(c[3])
        : "r"(a.x), "r"(a.y), "r"(a.z), "r"(a.w), "r"(b.x), "r"(b.y));
}

// =====================================================================
// K1 (mma.sync tf32, 3-term split): x(M x 128) @ [W_in|W_gate|W_lam]
//   Block tile M=128, N=64, K=128. 8 warps, warp tile 32x32.
//   A/B stored in smem in FRAGMENT ORDER (hi & lo), so mma-phase loads
//   are plain uint4/uint2, conflict-free.
// =====================================================================
// smem layout (bytes):
//   AHI: 16384 u32 @ 0        (atoms_m=8, ksteps=16, 32 lanes, 4 regs)
//   ALO: 16384 u32 @ 65536
//   BHI:  8192 u32 @ 131072   (atoms_n=8, ksteps=16, 32 lanes, 2 regs)
//   BLO:  8192 u32 @ 163840
#define K1_SMEM 196608

__global__ void __launch_bounds__(256, 1)
k1_mma(const float* __restrict__ x,
       const float* __restrict__ Win, const float* __restrict__ bin,
       const float* __restrict__ Wl,  const float* __restrict__ bl,
       const float* __restrict__ Wg,  const float* __restrict__ bg)
{
    extern __shared__ uint32_t smu[];
    uint32_t* AHI = smu;
    uint32_t* ALO = smu + 16384;
    uint32_t* BHI = smu + 32768;
    uint32_t* BLO = smu + 40960;

    const int tid  = threadIdx.x;
    const int wid  = tid >> 5;
    const int lane = tid & 31;
    const int nt = blockIdx.x;               // 0..9
    const int m0 = blockIdx.y * 128;

    // region select (uniform per block)
    const float* Wsrc; const float* bias; int ldn, c0;
    if (nt < 4)      { Wsrc = Win; bias = bin; ldn = 256; c0 = nt * 64; }
    else if (nt < 8) { Wsrc = Wg;  bias = bg;  ldn = 256; c0 = (nt - 4) * 64; }
    else             { Wsrc = Wl;  bias = bl;  ldn = 128; c0 = (nt - 8) * 64; }

    // ---- fill A fragments: element (m, k) of x tile
    {
        const float4* xr = (const float4*)(x + (size_t)m0 * 128);
#pragma unroll
        for (int i = 0; i < 16; i++) {
            int idx = tid + i * 256;          // 0..4095 over (m, k4)
            int m  = idx >> 5;
            int k4 = idx & 31;
            float4 v = xr[idx];
            int atom = m >> 4, r = m & 15, g = r & 7, hi8 = r >> 3;
            int kstep = k4 >> 1, khi = k4 & 1;
            int basef = ((atom * 16 + kstep) * 32 + g * 4) * 4 + hi8 + 2 * khi;
            float e[4] = {v.x, v.y, v.z, v.w};
#pragma unroll
            for (int j = 0; j < 4; j++) {
                uint32_t h = cvt_tf32(e[j]);
                uint32_t l = cvt_tf32(e[j] - __uint_as_float(h));
                AHI[basef + j * 4] = h;
                ALO[basef + j * 4] = l;
            }
        }
    }
    // ---- fill B fragments: element (k, n) of W[k][c0+n]
    {
#pragma unroll
        for (int i = 0; i < 32; i++) {
            int idx = tid + i * 256;          // 0..8191 over (k, n)
            int k = idx >> 6;
            int n = idx & 63;
            float v = Wsrc[k * ldn + c0 + n];
            int atomn = n >> 3, g = n & 7;
            int kstep = k >> 3, kl = k & 7, tig = kl & 3, khi = kl >> 2;
            int fidx = ((atomn * 16 + kstep) * 32 + g * 4 + tig) * 2 + khi;
            uint32_t h = cvt_tf32(v);
            BHI[fidx] = h;
            BLO[fidx] = cvt_tf32(v - __uint_as_float(h));
        }
    }
    __syncthreads();

    // ---- mma phase: warp grid 4(m) x 2(n), warp tile 32x32
    const int warp_m = wid >> 1;
    const int warp_n = wid & 1;
    float c[2][4][4];
#pragma unroll
    for (int im = 0; im < 2; im++)
#pragma unroll
        for (int jn = 0; jn < 4; jn++)
#pragma unroll
            for (int q = 0; q < 4; q++) c[im][jn][q] = 0.f;

#pragma unroll 4
    for (int ks = 0; ks < 16; ks++) {
        uint4 ah[2], al[2];
#pragma unroll
        for (int im = 0; im < 2; im++) {
            int atom = warp_m * 2 + im;
            int o = ((atom * 16 + ks) * 32 + lane) * 4;
            ah[im] = *(const uint4*)&AHI[o];
            al[im] = *(const uint4*)&ALO[o];
        }
        uint2 bh[4], bl[4];
#pragma unroll
        for (int jn = 0; jn < 4; jn++) {
            int atomn = warp_n * 4 + jn;
            int o = ((atomn * 16 + ks) * 32 + lane) * 2;
            bh[jn] = *(const uint2*)&BHI[o];
            bl[jn] = *(const uint2*)&BLO[o];
        }
#pragma unroll
        for (int im = 0; im < 2; im++)
#pragma unroll
            for (int jn = 0; jn < 4; jn++) {
                mma_tf32(c[im][jn], ah[im], bh[jn]);
                mma_tf32(c[im][jn], ah[im], bl[jn]);
                mma_tf32(c[im][jn], al[im], bh[jn]);
            }
    }
    __syncthreads();   // A/B smem dead; reuse as staging

    // ---- stage C to smem (rows 128, stride 66 floats)
    {
        float* stage = (float*)smu;
        const int g = lane >> 2, tig = lane & 3;
#pragma unroll
        for (int im = 0; im < 2; im++) {
#pragma unroll
            for (int jn = 0; jn < 4; jn++) {
                int R0 = warp_m * 32 + im * 16 + g;
                int C0 = warp_n * 32 + jn * 8 + 2 * tig;
                *(float2*)&stage[R0 * 66 + C0]       = make_float2(c[im][jn][0], c[im][jn][1]);
                *(float2*)&stage[(R0 + 8) * 66 + C0] = make_float2(c[im][jn][2], c[im][jn][3]);
            }
        }
    }
    __syncthreads();

    // ---- coalesced store with bias + activation
    {
        const float* stage = (const float*)smu;
        const int row = tid >> 1;
        const int ch  = (tid & 1) * 32;
        const float* srcp = stage + row * 66 + ch;
        float v[32];
#pragma unroll
        for (int j = 0; j < 32; j++) v[j] = srcp[j] + bias[c0 + ch + j];
        if (nt < 8) {
#pragma unroll
            for (int j = 0; j < 32; j++) v[j] = v[j] * sigmoidf_(v[j]);   // silu
        } else {
#pragma unroll
            for (int j = 0; j < 32; j++) v[j] = sigmoidf_(v[j]);         // lambda
        }
        float* dst;
        if (nt < 4)      dst = g_inp  + (size_t)(m0 + row) * 256 + c0 + ch;
        else if (nt < 8) dst = g_gate + (size_t)(m0 + row) * 256 + c0 + ch;
        else             dst = g_lam  + (size_t)(m0 + row) * 128 + c0 + ch;
#pragma unroll
        for (int j = 0; j < 8; j++)
            *(float4*)(dst + j * 4) = make_float4(v[4*j], v[4*j+1], v[4*j+2], v[4*j+3]);
    }
}

// =====================================================================
// Scan kernel (templated on axis): per CTA, 64 lines cached in smem;
// warps 0-1 run forward scans, warps 2-3 run reverse scans concurrently;
// then the summed result is written (RMW for axis 1).
//   axis 0 (H): line = (w*8+b, d), step stride = 131072 (float2 units)
//   axis 1 (W): line = (h, b, d),  step stride = 1024
// smem: sInp float2[128][64] | sLam float[128][64] | sHf float2[128][64]
//       | sHr float2[128][64]  = 229376 bytes
// =====================================================================
#define SCAN_SMEM 229376

template<int AXIS>
__global__ void __launch_bounds__(128, 1)
kscan(const float* __restrict__ thf, const float* __restrict__ thr_)
{
    extern __shared__ char smraw[];
    float2* sInp = (float2*)smraw;                 // [128][64]
    float*  sLam = (float*)(smraw + 65536);        // [128][64]
    float2* sHf  = (float2*)(smraw + 98304);       // [128][64]
    float2* sHr  = (float2*)(smraw + 163840);      // [128][64]

    const int tid = threadIdx.x;
    const int bi  = blockIdx.x;
    const int d0  = (bi & 1) * 64;

    size_t base;   // in float2 units for inp/acc; same number in float units for lam
    if (AXIS == 0) { int wb = bi >> 1; base = (size_t)wb * 128 + d0; }
    else           { int hb = bi >> 1; int h = hb >> 3; int b = hb & 7;
                     base = ((size_t)h * 1024 + b) * 128 + d0; }
    const int stride = (AXIS == 0) ? 131072 : 1024;

    // ---- cooperative load: inp (float2 as float4) and lam (float4)
    {
        const float4* inp4 = (const float4*)g_inp;
        float4* sInp4 = (float4*)sInp;
#pragma unroll
        for (int i = 0; i < 32; i++) {
            int idx = tid + i * 128;           // (h, q) : h=idx>>5, q=idx&31
            int h = idx >> 5, q = idx & 31;
            sInp4[idx] = inp4[(base + (size_t)h * stride) / 2 + q];
        }
        const float4* lam4 = (const float4*)g_lam;
        float4* sLam4 = (float4*)sLam;
#pragma unroll
        for (int i = 0; i < 16; i++) {
            int idx = tid + i * 128;           // h=idx>>4, q=idx&15
            int h = idx >> 4, q = idx & 15;
            sLam4[idx] = lam4[(base + (size_t)h * stride) / 4 + q];
        }
    }
    __syncthreads();

    // ---- serial scans: warps 0-1 forward (theta_f), warps 2-3 reverse (theta_r)
    if (tid < 64) {
        const int dl = tid;
        float t = thf[d0 + dl];
        float cf = cosf(t), sf = sinf(t);
        float hr = 0.f, hi = 0.f;
#pragma unroll 4
        for (int h = 0; h < 128; h++) {
            float lam = sLam[h * 64 + dl];
            float2 p  = sInp[h * 64 + dl];
            float a = lam * cf, b = lam * sf, om = 1.f - lam;
            float nr = a * hr - b * hi + om * p.x;
            float ni = a * hi + b * hr + om * p.y;
            hr = nr; hi = ni;
            sHf[h * 64 + dl] = make_float2(hr, hi);
        }
    } else {
        const int dl = tid - 64;
        float t = thr_[d0 + dl];
        float cr = cosf(t), sr = sinf(t);
        float hr = 0.f, hi = 0.f;
#pragma unroll 4
        for (int j = 0; j < 128; j++) {
            int h = 127 - j;
            float lam = sLam[h * 64 + dl];
            float2 p  = sInp[h * 64 + dl];
            float a = lam * cr, b = lam * sr, om = 1.f - lam;
            float nr = a * hr - b * hi + om * p.x;
            float ni = a * hi + b * hr + om * p.y;
            hr = nr; hi = ni;
            sHr[h * 64 + dl] = make_float2(hr, hi);
        }
    }
    __syncthreads();

    // ---- sum (+ optional RMW) and store, coalesced float4
    {
        float4* acc4 = (float4*)g_acc;
        const float4* sHf4 = (const float4*)sHf;
        const float4* sHr4 = (const float4*)sHr;
#pragma unroll
        for (int i = 0; i < 32; i++) {
            int idx = tid + i * 128;
            int h = idx >> 5, q = idx & 31;
            size_t gi = base + (size_t)h * stride;   // float2 units; float4 idx = gi/2+q
            float4 a = sHf4[idx];
            float4 b = sHr4[idx];
            float4 v = make_float4(a.x + b.x, a.y + b.y, a.z + b.z, a.w + b.w);
            if (AXIS == 1) {
                float4 o = acc4[gi / 2 + q];
                v.x += o.x; v.y += o.y; v.z += o.z; v.w += o.w;
            }
            acc4[gi / 2 + q] = v;
        }
    }
}

// =====================================================================
// K4: LN(256)*ln_w+ln_b, *gate -> feat smem; GEMM @ W_out + b_out. FFMA2.
// (unchanged from round 4 — known good, 385 us)
// =====================================================================
#define FLD 260

__global__ void __launch_bounds__(256, 1)
k4_out_gemm(const float* __restrict__ Wout, const float* __restrict__ bout,
            const float* __restrict__ lnw,  const float* __restrict__ lnb,
            float* __restrict__ out)
{
    extern __shared__ float smf[];
    float* feat = smf;
    float* Ws   = smf + 64 * FLD;

    const int tid = threadIdx.x;
    const int m0 = blockIdx.x * 64;

    {
        float4* Ws4 = (float4*)Ws;
        const float4* W4 = (const float4*)Wout;
#pragma unroll
        for (int t = 0; t < 32; t++) Ws4[tid + t * 256] = W4[tid + t * 256];
    }

    {
        int r = tid >> 2;
        int q = tid & 3;
        int row = m0 + r;
        const float2* accp = g_acc + (size_t)row * 128;

        float sum = 0.f, ss = 0.f;
#pragma unroll
        for (int t = 0; t < 32; t++) {
            int dd = q + t * 4;
            float2 v = accp[dd];
            sum += v.x + v.y;
            ss  += v.x * v.x + v.y * v.y;
        }
        sum += __shfl_xor_sync(0xffffffffu, sum, 1);
        sum += __shfl_xor_sync(0xffffffffu, sum, 2);
        ss  += __shfl_xor_sync(0xffffffffu, ss, 1);
        ss  += __shfl_xor_sync(0xffffffffu, ss, 2);

        float mu   = sum * (1.0f / 256.0f);
        float var  = ss * (1.0f / 256.0f) - mu * mu;
        float rstd = rsqrtf(var + 1e-5f);

        const float* gr = g_gate + (size_t)row * 256;
#pragma unroll
        for (int t = 0; t < 32; t++) {
            int dd = q + t * 4;
            float2 v = accp[dd];
            float fr = ((v.x - mu) * rstd * lnw[dd]       + lnb[dd])       * gr[dd];
            float fi = ((v.y - mu) * rstd * lnw[128 + dd] + lnb[128 + dd]) * gr[128 + dd];
            feat[r * FLD + dd]       = fr;
            feat[r * FLD + 128 + dd] = fi;
        }
    }
    __syncthreads();

    const int ty = tid >> 4;
    const int tx = tid & 15;
    const unsigned ws_base = (unsigned)__cvta_generic_to_shared(Ws) + tx * 32;

    ull acc[4][4];
#pragma unroll
    for (int i = 0; i < 4; i++)
#pragma unroll
        for (int p = 0; p < 4; p++) acc[i][p] = 0ULL;

#pragma unroll 2
    for (int kc = 0; kc < 64; kc++) {
        ull b[4][4];
#pragma unroll
        for (int kk = 0; kk < 4; kk++) {
            unsigned ad = ws_base + (unsigned)((kc * 4 + kk) * 512);
            lds2(b[kk][0], b[kk][1], ad);
            lds2(b[kk][2], b[kk][3], ad + 16);
        }
#pragma unroll
        for (int i = 0; i < 4; i++) {
            float4 a = *(const float4*)&feat[(ty * 4 + i) * FLD + kc * 4];
            ull a0 = pack2(a.x), a1 = pack2(a.y), a2 = pack2(a.z), a3 = pack2(a.w);
#pragma unroll
            for (int p = 0; p < 4; p++) {
                ffma2(acc[i][p], a0, b[0][p]);
                ffma2(acc[i][p], a1, b[1][p]);
                ffma2(acc[i][p], a2, b[2][p]);
                ffma2(acc[i][p], a3, b[3][p]);
            }
        }
    }

    float4 blo = *(const float4*)&bout[tx * 8];
    float4 bhi = *(const float4*)&bout[tx * 8 + 4];
    float bias[8] = {blo.x, blo.y, blo.z, blo.w, bhi.x, bhi.y, bhi.z, bhi.w};
#pragma unroll
    for (int i = 0; i < 4; i++) {
        int row = m0 + ty * 4 + i;
        float v[8];
#pragma unroll
        for (int p = 0; p < 4; p++) { float2 u = unpack2(acc[i][p]); v[2*p] = u.x; v[2*p+1] = u.y; }
#pragma unroll
        for (int j = 0; j < 8; j++) v[j] += bias[j];
        float* dst = out + (size_t)row * 128 + tx * 8;
        *(float4*)dst       = make_float4(v[0], v[1], v[2], v[3]);
        *(float4*)(dst + 4) = make_float4(v[4], v[5], v[6], v[7]);
    }
}

// =====================================================================
extern "C" void kernel_launch(void* const* d_in, const int* in_sizes, int n_in,
                              void* d_out, int out_size)
{
    const float* x    = (const float*)d_in[0];
    const float* Win  = (const float*)d_in[1];
    const float* bin  = (const float*)d_in[2];
    const float* Wl   = (const float*)d_in[3];
    const float* bl   = (const float*)d_in[4];
    const float* thf  = (const float*)d_in[5];
    const float* thr_ = (const float*)d_in[6];
    const float* Wg   = (const float*)d_in[7];
    const float* bg   = (const float*)d_in[8];
    const float* Wout = (const float*)d_in[9];
    const float* bout = (const float*)d_in[10];
    const float* lnw  = (const float*)d_in[11];
    const float* lnb  = (const float*)d_in[12];
    float* out = (float*)d_out;

    const int SM4 = (64 * FLD + 256 * 128) * 4;        // 197632
    cudaFuncSetAttribute(k1_mma,      cudaFuncAttributeMaxDynamicSharedMemorySize, K1_SMEM);
    cudaFuncSetAttribute(kscan<0>,    cudaFuncAttributeMaxDynamicSharedMemorySize, SCAN_SMEM);
    cudaFuncSetAttribute(kscan<1>,    cudaFuncAttributeMaxDynamicSharedMemorySize, SCAN_SMEM);
    cudaFuncSetAttribute(k4_out_gemm, cudaFuncAttributeMaxDynamicSharedMemorySize, SM4);

    dim3 g1(10, MM / 128);                             // (10, 1024)
    k1_mma<<<g1, 256, K1_SMEM>>>(x, Win, bin, Wl, bl, Wg, bg);

    kscan<0><<<2048, 128, SCAN_SMEM>>>(thf, thr_);     // H-axis, writes acc
    kscan<1><<<2048, 128, SCAN_SMEM>>>(thf, thr_);     // W-axis, RMW acc

    k4_out_gemm<<<MM / 64, 256, SM4>>>(Wout, bout, lnw, lnb, out);
}

// round 7
// speedup vs baseline: 1.2978x; 1.2978x over previous
#include <cuda_runtime.h>
#include <math.h>
#include <stdint.h>

// Problem dims
#define HH 128
#define WW 128
#define BB 8
#define DD 128
#define MM (HH*WW*BB)          // 131072 rows

typedef unsigned long long ull;

// ---------------- scratch (no cudaMalloc allowed) ----------------
__device__ float  g_inp [MM * 256];   // silu(x@W_in + b_in), interleaved re/im
__device__ float  g_gate[MM * 256];   // silu(x@W_gate + b_gate)
__device__ float  g_lam [MM * 128];   // sigmoid(x@W_lambda + b_lambda)
__device__ float2 g_acc [MM * 128];   // sum of 4 scans

static __device__ __forceinline__ float sigmoidf_(float v) {
    return 1.0f / (1.0f + expf(-v));
}

// ---------------- packed fp32x2 helpers ----------------
static __device__ __forceinline__ ull pack2(float v) {
    ull r; asm("mov.b64 %0, {%1, %1};" : "=l"(r) : "f"(v)); return r;
}
static __device__ __forceinline__ void ffma2(ull &d, ull a, ull b) {
    asm("fma.rn.f32x2 %0, %1, %2, %0;" : "+l"(d) : "l"(a), "l"(b));
}
static __device__ __forceinline__ void lds2(ull &a, ull &b, unsigned addr) {
    asm volatile("ld.shared.v2.b64 {%0, %1}, [%2];" : "=l"(a), "=l"(b) : "r"(addr));
}
static __device__ __forceinline__ float2 unpack2(ull v) {
    float2 r; asm("mov.b64 {%0, %1}, %2;" : "=f"(r.x), "=f"(r.y) : "l"(v)); return r;
}

// =====================================================================
// K1: x(M x 128) @ [W_in | W_gate | W_lambda](128 x 640)  + bias + act
//     BM=128, BN=128, K=128. 256 threads, 8x8 microtile, FFMA2.
//     (round-4 version, known good)
// =====================================================================
__global__ void __launch_bounds__(256, 1)
k1_in_gemm(const float* __restrict__ x,
           const float* __restrict__ Win, const float* __restrict__ bin,
           const float* __restrict__ Wl,  const float* __restrict__ bl,
           const float* __restrict__ Wg,  const float* __restrict__ bg)
{
    extern __shared__ float sm[];
    float* As = sm;              // [128][128] row-major (m, k)
    float* Bs = sm + 128 * 128;  // [128][128] (k, n)

    const int tid = threadIdx.x;
    const int m0 = blockIdx.y * 128;
    const int n0 = blockIdx.x * 128;

    {
        const float4* xr = (const float4*)(x + (size_t)m0 * 128);
        float4* As4 = (float4*)As;
#pragma unroll
        for (int t = 0; t < 16; t++) As4[tid + t * 256] = xr[tid + t * 256];
    }
    {
        const float* Wsrc; int ldn, c0;
        if (n0 < 256)      { Wsrc = Win; ldn = 256; c0 = n0; }
        else if (n0 < 512) { Wsrc = Wg;  ldn = 256; c0 = n0 - 256; }
        else               { Wsrc = Wl;  ldn = 128; c0 = 0; }
        float4* Bs4 = (float4*)Bs;
#pragma unroll
        for (int t = 0; t < 16; t++) {
            int idx = tid + t * 256;
            int k = idx >> 5, n4 = idx & 31;
            Bs4[idx] = *(const float4*)&Wsrc[k * ldn + c0 + n4 * 4];
        }
    }
    __syncthreads();

    const int ty = tid >> 4;
    const int tx = tid & 15;
    const unsigned bs_base = (unsigned)__cvta_generic_to_shared(Bs) + tx * 32;
    const float4* As4c = (const float4*)As;

    ull acc[8][4];
#pragma unroll
    for (int i = 0; i < 8; i++)
#pragma unroll
        for (int p = 0; p < 4; p++) acc[i][p] = 0ULL;

#pragma unroll 2
    for (int kc = 0; kc < 32; kc++) {
        ull b[4][4];
#pragma unroll
        for (int kk = 0; kk < 4; kk++) {
            unsigned ad = bs_base + (unsigned)((kc * 4 + kk) * 512);
            lds2(b[kk][0], b[kk][1], ad);
            lds2(b[kk][2], b[kk][3], ad + 16);
        }
#pragma unroll
        for (int i = 0; i < 8; i++) {
            float4 a = As4c[(ty * 8 + i) * 32 + kc];
            ull a0 = pack2(a.x), a1 = pack2(a.y), a2 = pack2(a.z), a3 = pack2(a.w);
#pragma unroll
            for (int p = 0; p < 4; p++) {
                ffma2(acc[i][p], a0, b[0][p]);
                ffma2(acc[i][p], a1, b[1][p]);
                ffma2(acc[i][p], a2, b[2][p]);
                ffma2(acc[i][p], a3, b[3][p]);
            }
        }
    }

    const int nb = tx * 8;
    if (n0 < 256) {
        const int n = n0 + nb;
        float4 blo = *(const float4*)&bin[n];
        float4 bhi = *(const float4*)&bin[n + 4];
        float bias[8] = {blo.x, blo.y, blo.z, blo.w, bhi.x, bhi.y, bhi.z, bhi.w};
#pragma unroll
        for (int i = 0; i < 8; i++) {
            int row = m0 + ty * 8 + i;
            float v[8];
#pragma unroll
            for (int p = 0; p < 4; p++) { float2 u = unpack2(acc[i][p]); v[2*p] = u.x; v[2*p+1] = u.y; }
#pragma unroll
            for (int j = 0; j < 8; j++) { float t = v[j] + bias[j]; v[j] = t * sigmoidf_(t); }
            float* dst = g_inp + (size_t)row * 256 + n;
            *(float4*)dst       = make_float4(v[0], v[1], v[2], v[3]);
            *(float4*)(dst + 4) = make_float4(v[4], v[5], v[6], v[7]);
        }
    } else if (n0 < 512) {
        const int n = n0 - 256 + nb;
        float4 blo = *(const float4*)&bg[n];
        float4 bhi = *(const float4*)&bg[n + 4];
        float bias[8] = {blo.x, blo.y, blo.z, blo.w, bhi.x, bhi.y, bhi.z, bhi.w};
#pragma unroll
        for (int i = 0; i < 8; i++) {
            int row = m0 + ty * 8 + i;
            float v[8];
#pragma unroll
            for (int p = 0; p < 4; p++) { float2 u = unpack2(acc[i][p]); v[2*p] = u.x; v[2*p+1] = u.y; }
#pragma unroll
            for (int j = 0; j < 8; j++) { float t = v[j] + bias[j]; v[j] = t * sigmoidf_(t); }
            float* dst = g_gate + (size_t)row * 256 + n;
            *(float4*)dst       = make_float4(v[0], v[1], v[2], v[3]);
            *(float4*)(dst + 4) = make_float4(v[4], v[5], v[6], v[7]);
        }
    } else {
        const int n = nb;
        float4 blo = *(const float4*)&bl[n];
        float4 bhi = *(const float4*)&bl[n + 4];
        float bias[8] = {blo.x, blo.y, blo.z, blo.w, bhi.x, bhi.y, bhi.z, bhi.w};
#pragma unroll
        for (int i = 0; i < 8; i++) {
            int row = m0 + ty * 8 + i;
            float v[8];
#pragma unroll
            for (int p = 0; p < 4; p++) { float2 u = unpack2(acc[i][p]); v[2*p] = u.x; v[2*p+1] = u.y; }
#pragma unroll
            for (int j = 0; j < 8; j++) v[j] = sigmoidf_(v[j] + bias[j]);
            float* dst = g_lam + (size_t)row * 128 + n;
            *(float4*)dst       = make_float4(v[0], v[1], v[2], v[3]);
            *(float4*)(dst + 4) = make_float4(v[4], v[5], v[6], v[7]);
        }
    }
}

// =====================================================================
// Scan kernel (templated on axis): per CTA, 64 lines cached in smem;
// warps 0-1 forward (theta_f), warps 2-3 reverse (theta_r), concurrent;
// summed result written once (RMW for axis 1).   (round-6 version)
// =====================================================================
#define SCAN_SMEM 229376

template<int AXIS>
__global__ void __launch_bounds__(128, 1)
kscan(const float* __restrict__ thf, const float* __restrict__ thr_)
{
    extern __shared__ char smraw[];
    float2* sInp = (float2*)smraw;                 // [128][64]
    float*  sLam = (float*)(smraw + 65536);        // [128][64]
    float2* sHf  = (float2*)(smraw + 98304);       // [128][64]
    float2* sHr  = (float2*)(smraw + 163840);      // [128][64]

    const int tid = threadIdx.x;
    const int bi  = blockIdx.x;
    const int d0  = (bi & 1) * 64;

    size_t base;
    if (AXIS == 0) { int wb = bi >> 1; base = (size_t)wb * 128 + d0; }
    else           { int hb = bi >> 1; int h = hb >> 3; int b = hb & 7;
                     base = ((size_t)h * 1024 + b) * 128 + d0; }
    const int stride = (AXIS == 0) ? 131072 : 1024;

    {
        const float4* inp4 = (const float4*)g_inp;
        float4* sInp4 = (float4*)sInp;
#pragma unroll
        for (int i = 0; i < 32; i++) {
            int idx = tid + i * 128;
            int h = idx >> 5, q = idx & 31;
            sInp4[idx] = inp4[(base + (size_t)h * stride) / 2 + q];
        }
        const float4* lam4 = (const float4*)g_lam;
        float4* sLam4 = (float4*)sLam;
#pragma unroll
        for (int i = 0; i < 16; i++) {
            int idx = tid + i * 128;
            int h = idx >> 4, q = idx & 15;
            sLam4[idx] = lam4[(base + (size_t)h * stride) / 4 + q];
        }
    }
    __syncthreads();

    if (tid < 64) {
        const int dl = tid;
        float t = thf[d0 + dl];
        float cf = cosf(t), sf = sinf(t);
        float hr = 0.f, hi = 0.f;
#pragma unroll 4
        for (int h = 0; h < 128; h++) {
            float lam = sLam[h * 64 + dl];
            float2 p  = sInp[h * 64 + dl];
            float a = lam * cf, b = lam * sf, om = 1.f - lam;
            float nr = a * hr - b * hi + om * p.x;
            float ni = a * hi + b * hr + om * p.y;
            hr = nr; hi = ni;
            sHf[h * 64 + dl] = make_float2(hr, hi);
        }
    } else {
        const int dl = tid - 64;
        float t = thr_[d0 + dl];
        float cr = cosf(t), sr = sinf(t);
        float hr = 0.f, hi = 0.f;
#pragma unroll 4
        for (int j = 0; j < 128; j++) {
            int h = 127 - j;
            float lam = sLam[h * 64 + dl];
            float2 p  = sInp[h * 64 + dl];
            float a = lam * cr, b = lam * sr, om = 1.f - lam;
            float nr = a * hr - b * hi + om * p.x;
            float ni = a * hi + b * hr + om * p.y;
            hr = nr; hi = ni;
            sHr[h * 64 + dl] = make_float2(hr, hi);
        }
    }
    __syncthreads();

    {
        float4* acc4 = (float4*)g_acc;
        const float4* sHf4 = (const float4*)sHf;
        const float4* sHr4 = (const float4*)sHr;
#pragma unroll
        for (int i = 0; i < 32; i++) {
            int idx = tid + i * 128;
            int h = idx >> 5, q = idx & 31;
            size_t gi = base + (size_t)h * stride;
            float4 a = sHf4[idx];
            float4 b = sHr4[idx];
            float4 v = make_float4(a.x + b.x, a.y + b.y, a.z + b.z, a.w + b.w);
            if (AXIS == 1) {
                float4 o = acc4[gi / 2 + q];
                v.x += o.x; v.y += o.y; v.z += o.z; v.w += o.w;
            }
            acc4[gi / 2 + q] = v;
        }
    }
}

// =====================================================================
// K4: LN(256)*ln_w+ln_b, *gate -> feat smem; GEMM @ W_out + b_out.
//     256 threads, 2-way split-K (128 threads each), 8x8 microtile, FFMA2.
// =====================================================================
#define FLD 260
#define STG 132   // stage row stride (floats)

__global__ void __launch_bounds__(256, 1)
k4_out_gemm(const float* __restrict__ Wout, const float* __restrict__ bout,
            const float* __restrict__ lnw,  const float* __restrict__ lnb,
            float* __restrict__ out)
{
    extern __shared__ float smf[];
    float* feat = smf;              // [64][FLD]
    float* Ws   = smf + 64 * FLD;   // [256][128]

    const int tid = threadIdx.x;
    const int m0 = blockIdx.x * 64;

    // ---- load W_out (256x128)
    {
        float4* Ws4 = (float4*)Ws;
        const float4* W4 = (const float4*)Wout;
#pragma unroll
        for (int t = 0; t < 32; t++) Ws4[tid + t * 256] = W4[tid + t * 256];
    }

    // ---- producer: LN stats + normalized, gated feature into smem
    {
        int r = tid >> 2;
        int q = tid & 3;
        int row = m0 + r;
        const float2* accp = g_acc + (size_t)row * 128;

        float sum = 0.f, ss = 0.f;
#pragma unroll
        for (int t = 0; t < 32; t++) {
            int dd = q + t * 4;
            float2 v = accp[dd];
            sum += v.x + v.y;
            ss  += v.x * v.x + v.y * v.y;
        }
        sum += __shfl_xor_sync(0xffffffffu, sum, 1);
        sum += __shfl_xor_sync(0xffffffffu, sum, 2);
        ss  += __shfl_xor_sync(0xffffffffu, ss, 1);
        ss  += __shfl_xor_sync(0xffffffffu, ss, 2);

        float mu   = sum * (1.0f / 256.0f);
        float var  = ss * (1.0f / 256.0f) - mu * mu;
        float rstd = rsqrtf(var + 1e-5f);

        const float* gr = g_gate + (size_t)row * 256;
#pragma unroll
        for (int t = 0; t < 32; t++) {
            int dd = q + t * 4;
            float2 v = accp[dd];
            float fr = ((v.x - mu) * rstd * lnw[dd]       + lnb[dd])       * gr[dd];
            float fi = ((v.y - mu) * rstd * lnw[128 + dd] + lnb[128 + dd]) * gr[128 + dd];
            feat[r * FLD + dd]       = fr;
            feat[r * FLD + 128 + dd] = fi;
        }
    }
    __syncthreads();

    // ---- GEMM: split-K. gid 0 -> kc [0,32), gid 1 -> kc [32,64).
    //      Each half: 128 threads, 8(ty) x 16(tx), 8x8 microtile.
    const int gid = tid >> 7;
    const int lt  = tid & 127;
    const int ty  = lt >> 4;     // rows ty*8
    const int tx  = lt & 15;     // cols tx*8
    const unsigned ws_base = (unsigned)__cvta_generic_to_shared(Ws) + tx * 32;

    ull acc[8][4];
#pragma unroll
    for (int i = 0; i < 8; i++)
#pragma unroll
        for (int p = 0; p < 4; p++) acc[i][p] = 0ULL;

    const int kc0 = gid * 32;
#pragma unroll 1
    for (int kc = kc0; kc < kc0 + 32; kc++) {
        ull b[4][4];
#pragma unroll
        for (int kk = 0; kk < 4; kk++) {
            unsigned ad = ws_base + (unsigned)((kc * 4 + kk) * 512);
            lds2(b[kk][0], b[kk][1], ad);
            lds2(b[kk][2], b[kk][3], ad + 16);
        }
#pragma unroll
        for (int i = 0; i < 8; i++) {
            float4 a = *(const float4*)&feat[(ty * 8 + i) * FLD + kc * 4];
            ull a0 = pack2(a.x), a1 = pack2(a.y), a2 = pack2(a.z), a3 = pack2(a.w);
#pragma unroll
            for (int p = 0; p < 4; p++) {
                ffma2(acc[i][p], a0, b[0][p]);
                ffma2(acc[i][p], a1, b[1][p]);
                ffma2(acc[i][p], a2, b[2][p]);
                ffma2(acc[i][p], a3, b[3][p]);
            }
        }
    }
    __syncthreads();   // feat dead; reuse as stage [64][STG]

    float* stage = smf;
    if (gid == 1) {
#pragma unroll
        for (int i = 0; i < 8; i++) {
            float v[8];
#pragma unroll
            for (int p = 0; p < 4; p++) { float2 u = unpack2(acc[i][p]); v[2*p] = u.x; v[2*p+1] = u.y; }
            float* sp = stage + (ty * 8 + i) * STG + tx * 8;
            *(float4*)sp       = make_float4(v[0], v[1], v[2], v[3]);
            *(float4*)(sp + 4) = make_float4(v[4], v[5], v[6], v[7]);
        }
    }
    __syncthreads();

    if (gid == 0) {
        float4 blo = *(const float4*)&bout[tx * 8];
        float4 bhi = *(const float4*)&bout[tx * 8 + 4];
        float bias[8] = {blo.x, blo.y, blo.z, blo.w, bhi.x, bhi.y, bhi.z, bhi.w};
#pragma unroll
        for (int i = 0; i < 8; i++) {
            const float* sp = stage + (ty * 8 + i) * STG + tx * 8;
            float4 s0 = *(const float4*)sp;
            float4 s1 = *(const float4*)(sp + 4);
            float s[8] = {s0.x, s0.y, s0.z, s0.w, s1.x, s1.y, s1.z, s1.w};
            float v[8];
#pragma unroll
            for (int p = 0; p < 4; p++) { float2 u = unpack2(acc[i][p]); v[2*p] = u.x; v[2*p+1] = u.y; }
#pragma unroll
            for (int j = 0; j < 8; j++) v[j] += s[j] + bias[j];
            float* dst = out + (size_t)(m0 + ty * 8 + i) * 128 + tx * 8;
            *(float4*)dst       = make_float4(v[0], v[1], v[2], v[3]);
            *(float4*)(dst + 4) = make_float4(v[4], v[5], v[6], v[7]);
        }
    }
}

// =====================================================================
extern "C" void kernel_launch(void* const* d_in, const int* in_sizes, int n_in,
                              void* d_out, int out_size)
{
    const float* x    = (const float*)d_in[0];
    const float* Win  = (const float*)d_in[1];
    const float* bin  = (const float*)d_in[2];
    const float* Wl   = (const float*)d_in[3];
    const float* bl   = (const float*)d_in[4];
    const float* thf  = (const float*)d_in[5];
    const float* thr_ = (const float*)d_in[6];
    const float* Wg   = (const float*)d_in[7];
    const float* bg   = (const float*)d_in[8];
    const float* Wout = (const float*)d_in[9];
    const float* bout = (const float*)d_in[10];
    const float* lnw  = (const float*)d_in[11];
    const float* lnb  = (const float*)d_in[12];
    float* out = (float*)d_out;

    const int SM1 = 128 * 128 * 2 * 4;                 // 131072
    const int SM4 = (64 * FLD + 256 * 128) * 4;        // 197632
    cudaFuncSetAttribute(k1_in_gemm,  cudaFuncAttributeMaxDynamicSharedMemorySize, SM1);
    cudaFuncSetAttribute(kscan<0>,    cudaFuncAttributeMaxDynamicSharedMemorySize, SCAN_SMEM);
    cudaFuncSetAttribute(kscan<1>,    cudaFuncAttributeMaxDynamicSharedMemorySize, SCAN_SMEM);
    cudaFuncSetAttribute(k4_out_gemm, cudaFuncAttributeMaxDynamicSharedMemorySize, SM4);

    dim3 g1(640 / 128, MM / 128);                      // (5, 1024)
    k1_in_gemm<<<g1, 256, SM1>>>(x, Win, bin, Wl, bl, Wg, bg);

    kscan<0><<<2048, 128, SCAN_SMEM>>>(thf, thr_);     // H-axis, writes acc
    kscan<1><<<2048, 128, SCAN_SMEM>>>(thf, thr_);     // W-axis, RMW acc

    k4_out_gemm<<<MM / 64, 256, SM4>>>(Wout, bout, lnw, lnb, out);
}

// round 8
// speedup vs baseline: 1.4377x; 1.1078x over previous
#include <cuda_runtime.h>
#include <math.h>
#include <stdint.h>

// Problem dims
#define HH 128
#define WW 128
#define BB 8
#define DD 128
#define MM (HH*WW*BB)          // 131072 rows

typedef unsigned long long ull;

// ---------------- scratch (no cudaMalloc allowed) ----------------
__device__ float  g_inp [MM * 256];   // silu(x@W_in + b_in), interleaved re/im
__device__ float  g_gate[MM * 256];   // silu(x@W_gate + b_gate)
__device__ float  g_lam [MM * 128];   // sigmoid(x@W_lambda + b_lambda)
__device__ float2 g_acc [MM * 128];   // sum of 4 scans

static __device__ __forceinline__ float sigmoidf_(float v) {
    return 1.0f / (1.0f + expf(-v));
}

// ---------------- packed fp32x2 helpers ----------------
static __device__ __forceinline__ ull pack2(float v) {
    ull r; asm("mov.b64 %0, {%1, %1};" : "=l"(r) : "f"(v)); return r;
}
static __device__ __forceinline__ void ffma2(ull &d, ull a, ull b) {
    asm("fma.rn.f32x2 %0, %1, %2, %0;" : "+l"(d) : "l"(a), "l"(b));
}
static __device__ __forceinline__ void lds2(ull &a, ull &b, unsigned addr) {
    asm volatile("ld.shared.v2.b64 {%0, %1}, [%2];" : "=l"(a), "=l"(b) : "r"(addr));
}
static __device__ __forceinline__ float2 unpack2(ull v) {
    float2 r; asm("mov.b64 {%0, %1}, %2;" : "=f"(r.x), "=f"(r.y) : "l"(v)); return r;
}

// =====================================================================
// K1: x(M x 128) @ [W_in | W_gate | W_lambda](128 x 640)  + bias + act
//     BM=128, BN=128, K=128. 512 threads (16 warps), 8x4 microtile.
//     A stored DUPLICATED in smem (pairs) -> FFMA2 A-operand is a direct
//     broadcast b64 load; no pack2 MOVs in the hot loop.
// smem: A_dup 128x128 ull = 131072 B | Bs 128x128 f32 = 65536 B
// =====================================================================
#define K1_SMEM 196608

__global__ void __launch_bounds__(512, 1)
k1_in_gemm(const float* __restrict__ x,
           const float* __restrict__ Win, const float* __restrict__ bin,
           const float* __restrict__ Wl,  const float* __restrict__ bl,
           const float* __restrict__ Wg,  const float* __restrict__ bg)
{
    extern __shared__ char smraw[];
    ull*   Ad = (ull*)smraw;                  // [128 m][128 k] duplicated pairs
    float* Bs = (float*)(smraw + 131072);     // [128 k][128 n]

    const int tid = threadIdx.x;
    const int m0 = blockIdx.y * 128;
    const int n0 = blockIdx.x * 128;

    // region select (uniform per block; BN=128 aligns with region boundaries)
    const float* Wsrc; const float* bias; int ldn, c0;
    if (n0 < 256)      { Wsrc = Win; bias = bin; ldn = 256; c0 = n0; }
    else if (n0 < 512) { Wsrc = Wg;  bias = bg;  ldn = 256; c0 = n0 - 256; }
    else               { Wsrc = Wl;  bias = bl;  ldn = 128; c0 = 0; }

    // ---- fill A_dup (coalesced float4 reads; 2x STS.128 per float4)
    {
        const float4* xr = (const float4*)(x + (size_t)m0 * 128);
#pragma unroll
        for (int i = 0; i < 8; i++) {
            int idx = tid + i * 512;          // m = idx>>5, k4 = idx&31
            int m = idx >> 5, k4 = idx & 31;
            float4 v = xr[idx];
            float4* dst = (float4*)(Ad + m * 128 + k4 * 4);
            dst[0] = make_float4(v.x, v.x, v.y, v.y);
            dst[1] = make_float4(v.z, v.z, v.w, v.w);
        }
    }
    // ---- fill Bs
    {
        float4* Bs4 = (float4*)Bs;
#pragma unroll
        for (int i = 0; i < 8; i++) {
            int idx = tid + i * 512;
            int k = idx >> 5, n4 = idx & 31;
            Bs4[idx] = *(const float4*)&Wsrc[k * ldn + c0 + n4 * 4];
        }
    }
    __syncthreads();

    const int ty = tid >> 5;     // 0..15 -> rows ty*8
    const int tx = tid & 31;     // 0..31 -> cols tx*4
    const unsigned bs_base = (unsigned)__cvta_generic_to_shared(Bs) + tx * 16;
    const unsigned ad_base = (unsigned)__cvta_generic_to_shared(Ad) + (ty * 8) * 1024;

    ull acc[8][2];
#pragma unroll
    for (int i = 0; i < 8; i++) { acc[i][0] = 0ULL; acc[i][1] = 0ULL; }

#pragma unroll 4
    for (int kc = 0; kc < 32; kc++) {
        ull b[4][2];
#pragma unroll
        for (int kk = 0; kk < 4; kk++)
            lds2(b[kk][0], b[kk][1], bs_base + (unsigned)((kc * 4 + kk) * 512));
#pragma unroll
        for (int i = 0; i < 8; i++) {
            unsigned aad = ad_base + (unsigned)(i * 1024 + kc * 32);
            ull a0, a1, a2, a3;
            lds2(a0, a1, aad);
            lds2(a2, a3, aad + 16);
            ffma2(acc[i][0], a0, b[0][0]); ffma2(acc[i][1], a0, b[0][1]);
            ffma2(acc[i][0], a1, b[1][0]); ffma2(acc[i][1], a1, b[1][1]);
            ffma2(acc[i][0], a2, b[2][0]); ffma2(acc[i][1], a2, b[2][1]);
            ffma2(acc[i][0], a3, b[3][0]); ffma2(acc[i][1], a3, b[3][1]);
        }
    }

    // ---- epilogue: 4 cols per thread, float4 stores
    {
        const int nb = tx * 4;
        float4 b4 = *(const float4*)&bias[c0 + nb];
        float bv[4] = {b4.x, b4.y, b4.z, b4.w};
#pragma unroll
        for (int i = 0; i < 8; i++) {
            int row = m0 + ty * 8 + i;
            float v[4];
            float2 u0 = unpack2(acc[i][0]); v[0] = u0.x + bv[0]; v[1] = u0.y + bv[1];
            float2 u1 = unpack2(acc[i][1]); v[2] = u1.x + bv[2]; v[3] = u1.y + bv[3];
            float* dst;
            if (n0 < 512) {
#pragma unroll
                for (int j = 0; j < 4; j++) v[j] = v[j] * sigmoidf_(v[j]);   // silu
                dst = (n0 < 256 ? g_inp : g_gate) + (size_t)row * 256 + c0 + nb;
            } else {
#pragma unroll
                for (int j = 0; j < 4; j++) v[j] = sigmoidf_(v[j]);          // lambda
                dst = g_lam + (size_t)row * 128 + nb;
            }
            *(float4*)dst = make_float4(v[0], v[1], v[2], v[3]);
        }
    }
}

// =====================================================================
// K2: scans along H (axis 0). fwd(theta_f) writes acc; rev(theta_r) RMW.
// (round-4 version, known good)
// =====================================================================
__global__ void k2_hscan(const float* __restrict__ thf, const float* __restrict__ thr_)
{
    int idx = blockIdx.x * blockDim.x + threadIdx.x;
    int d  = idx & 127;
    int wb = idx >> 7;
    int base = wb * 128 + d;

    const float2* __restrict__ inp2 = (const float2*)g_inp;

    {
        float t = thf[d];
        float cf = cosf(t), sf = sinf(t);
        float hr = 0.f, hi = 0.f;
        int off = base;
#pragma unroll 4
        for (int h = 0; h < 128; h++, off += 131072) {
            float lam = g_lam[off];
            float2 p  = inp2[off];
            float a = lam * cf, b = lam * sf, om = 1.f - lam;
            float nr = a * hr - b * hi + om * p.x;
            float ni = a * hi + b * hr + om * p.y;
            hr = nr; hi = ni;
            g_acc[off] = make_float2(hr, hi);
        }
    }
    {
        float t = thr_[d];
        float cr = cosf(t), sr = sinf(t);
        float hr = 0.f, hi = 0.f;
        int off = base + 127 * 131072;
#pragma unroll 4
        for (int h = 0; h < 128; h++, off -= 131072) {
            float lam = g_lam[off];
            float2 p  = inp2[off];
            float a = lam * cr, b = lam * sr, om = 1.f - lam;
            float nr = a * hr - b * hi + om * p.x;
            float ni = a * hi + b * hr + om * p.y;
            hr = nr; hi = ni;
            float2 acc = g_acc[off];
            acc.x += hr; acc.y += hi;
            g_acc[off] = acc;
        }
    }
}

// =====================================================================
// K3: scans along W (axis 1). Both directions RMW into acc.
// (round-4 version, known good)
// =====================================================================
__global__ void k3_wscan(const float* __restrict__ thf, const float* __restrict__ thr_)
{
    int idx = blockIdx.x * blockDim.x + threadIdx.x;
    int d = idx & 127;
    int b = (idx >> 7) & 7;
    int h = idx >> 10;
    int base = (h * 1024 + b) * 128 + d;

    const float2* __restrict__ inp2 = (const float2*)g_inp;

    {
        float t = thf[d];
        float cf = cosf(t), sf = sinf(t);
        float hr = 0.f, hi = 0.f;
        int off = base;
#pragma unroll 4
        for (int w = 0; w < 128; w++, off += 1024) {
            float lam = g_lam[off];
            float2 p  = inp2[off];
            float a = lam * cf, bb = lam * sf, om = 1.f - lam;
            float nr = a * hr - bb * hi + om * p.x;
            float ni = a * hi + bb * hr + om * p.y;
            hr = nr; hi = ni;
            float2 acc = g_acc[off];
            acc.x += hr; acc.y += hi;
            g_acc[off] = acc;
        }
    }
    {
        float t = thr_[d];
        float cr = cosf(t), sr = sinf(t);
        float hr = 0.f, hi = 0.f;
        int off = base + 127 * 1024;
#pragma unroll 4
        for (int w = 0; w < 128; w++, off -= 1024) {
            float lam = g_lam[off];
            float2 p  = inp2[off];
            float a = lam * cr, bb = lam * sr, om = 1.f - lam;
            float nr = a * hr - bb * hi + om * p.x;
            float ni = a * hi + bb * hr + om * p.y;
            hr = nr; hi = ni;
            float2 acc = g_acc[off];
            acc.x += hr; acc.y += hi;
            g_acc[off] = acc;
        }
    }
}

// =====================================================================
// K4: LN(256)*ln_w+ln_b, *gate -> feat smem; GEMM @ W_out + b_out.
//     512 threads (16 warps), 4x4 microtile, FFMA2.
// =====================================================================
#define FLD 260

__global__ void __launch_bounds__(512, 1)
k4_out_gemm(const float* __restrict__ Wout, const float* __restrict__ bout,
            const float* __restrict__ lnw,  const float* __restrict__ lnb,
            float* __restrict__ out)
{
    extern __shared__ float smf[];
    float* feat = smf;              // [64][FLD]
    float* Ws   = smf + 64 * FLD;   // [256][128]

    const int tid = threadIdx.x;
    const int m0 = blockIdx.x * 64;

    // ---- load W_out (256x128)
    {
        float4* Ws4 = (float4*)Ws;
        const float4* W4 = (const float4*)Wout;
#pragma unroll
        for (int t = 0; t < 16; t++) Ws4[tid + t * 512] = W4[tid + t * 512];
    }

    // ---- producer: LN stats + normalized, gated feature (8 lanes/row)
    {
        int r = tid >> 3;          // local row 0..63
        int q = tid & 7;           // 8 lanes cooperate per row
        int row = m0 + r;
        const float2* accp = g_acc + (size_t)row * 128;

        float sum = 0.f, ss = 0.f;
#pragma unroll
        for (int t = 0; t < 16; t++) {
            int dd = q + t * 8;
            float2 v = accp[dd];
            sum += v.x + v.y;
            ss  += v.x * v.x + v.y * v.y;
        }
        sum += __shfl_xor_sync(0xffffffffu, sum, 1);
        sum += __shfl_xor_sync(0xffffffffu, sum, 2);
        sum += __shfl_xor_sync(0xffffffffu, sum, 4);
        ss  += __shfl_xor_sync(0xffffffffu, ss, 1);
        ss  += __shfl_xor_sync(0xffffffffu, ss, 2);
        ss  += __shfl_xor_sync(0xffffffffu, ss, 4);

        float mu   = sum * (1.0f / 256.0f);
        float var  = ss * (1.0f / 256.0f) - mu * mu;
        float rstd = rsqrtf(var + 1e-5f);

        const float* gr = g_gate + (size_t)row * 256;
#pragma unroll
        for (int t = 0; t < 16; t++) {
            int dd = q + t * 8;
            float2 v = accp[dd];
            float fr = ((v.x - mu) * rstd * lnw[dd]       + lnb[dd])       * gr[dd];
            float fi = ((v.y - mu) * rstd * lnw[128 + dd] + lnb[128 + dd]) * gr[128 + dd];
            feat[r * FLD + dd]       = fr;
            feat[r * FLD + 128 + dd] = fi;
        }
    }
    __syncthreads();

    // ---- GEMM: feat(64x256) @ Ws(256x128); 16(ty) x 32(tx), 4x4 microtile
    const int ty = tid >> 5;     // rows ty*4
    const int tx = tid & 31;     // cols tx*4
    const unsigned ws_base = (unsigned)__cvta_generic_to_shared(Ws) + tx * 16;

    ull acc[4][2];
#pragma unroll
    for (int i = 0; i < 4; i++) { acc[i][0] = 0ULL; acc[i][1] = 0ULL; }

#pragma unroll 4
    for (int kc = 0; kc < 64; kc++) {
        ull b[4][2];
#pragma unroll
        for (int kk = 0; kk < 4; kk++)
            lds2(b[kk][0], b[kk][1], ws_base + (unsigned)((kc * 4 + kk) * 512));
#pragma unroll
        for (int i = 0; i < 4; i++) {
            float4 a = *(const float4*)&feat[(ty * 4 + i) * FLD + kc * 4];
            ull a0 = pack2(a.x), a1 = pack2(a.y), a2 = pack2(a.z), a3 = pack2(a.w);
            ffma2(acc[i][0], a0, b[0][0]); ffma2(acc[i][1], a0, b[0][1]);
            ffma2(acc[i][0], a1, b[1][0]); ffma2(acc[i][1], a1, b[1][1]);
            ffma2(acc[i][0], a2, b[2][0]); ffma2(acc[i][1], a2, b[2][1]);
            ffma2(acc[i][0], a3, b[3][0]); ffma2(acc[i][1], a3, b[3][1]);
        }
    }

    // ---- epilogue: 4 cols per thread, float4 stores
    {
        float4 b4 = *(const float4*)&bout[tx * 4];
#pragma unroll
        for (int i = 0; i < 4; i++) {
            int row = m0 + ty * 4 + i;
            float2 u0 = unpack2(acc[i][0]);
            float2 u1 = unpack2(acc[i][1]);
            float* dst = out + (size_t)row * 128 + tx * 4;
            *(float4*)dst = make_float4(u0.x + b4.x, u0.y + b4.y,
                                        u1.x + b4.z, u1.y + b4.w);
        }
    }
}

// =====================================================================
extern "C" void kernel_launch(void* const* d_in, const int* in_sizes, int n_in,
                              void* d_out, int out_size)
{
    const float* x    = (const float*)d_in[0];
    const float* Win  = (const float*)d_in[1];
    const float* bin  = (const float*)d_in[2];
    const float* Wl   = (const float*)d_in[3];
    const float* bl   = (const float*)d_in[4];
    const float* thf  = (const float*)d_in[5];
    const float* thr_ = (const float*)d_in[6];
    const float* Wg   = (const float*)d_in[7];
    const float* bg   = (const float*)d_in[8];
    const float* Wout = (const float*)d_in[9];
    const float* bout = (const float*)d_in[10];
    const float* lnw  = (const float*)d_in[11];
    const float* lnb  = (const float*)d_in[12];
    float* out = (float*)d_out;

    const int SM4 = (64 * FLD + 256 * 128) * 4;        // 197632
    cudaFuncSetAttribute(k1_in_gemm,  cudaFuncAttributeMaxDynamicSharedMemorySize, K1_SMEM);
    cudaFuncSetAttribute(k4_out_gemm, cudaFuncAttributeMaxDynamicSharedMemorySize, SM4);

    dim3 g1(640 / 128, MM / 128);                      // (5, 1024)
    k1_in_gemm<<<g1, 512, K1_SMEM>>>(x, Win, bin, Wl, bl, Wg, bg);

    k2_hscan<<<MM / 256, 256>>>(thf, thr_);
    k3_wscan<<<MM / 256, 256>>>(thf, thr_);

    k4_out_gemm<<<MM / 64, 512, SM4>>>(Wout, bout, lnw, lnb, out);
}

// round 9
// speedup vs baseline: 1.6313x; 1.1346x over previous
#include <cuda_runtime.h>
#include <math.h>
#include <stdint.h>

// Problem dims
#define HH 128
#define WW 128
#define BB 8
#define DD 128
#define MM (HH*WW*BB)          // 131072 rows

typedef unsigned long long ull;

// ---------------- scratch (no cudaMalloc allowed) ----------------
__device__ float  g_inp [MM * 256];   // silu(x@W_in + b_in), interleaved re/im
__device__ float  g_gate[MM * 256];   // silu(x@W_gate + b_gate)
__device__ float  g_lam [MM * 128];   // sigmoid(x@W_lambda + b_lambda)
__device__ float2 g_acc [MM * 128];   // sum of 4 scans

static __device__ __forceinline__ float sigmoidf_(float v) {
    return 1.0f / (1.0f + expf(-v));
}

// ---------------- packed fp32x2 helpers ----------------
static __device__ __forceinline__ ull pack2(float v) {
    ull r; asm("mov.b64 %0, {%1, %1};" : "=l"(r) : "f"(v)); return r;
}
static __device__ __forceinline__ void ffma2(ull &d, ull a, ull b) {
    asm("fma.rn.f32x2 %0, %1, %2, %0;" : "+l"(d) : "l"(a), "l"(b));
}
static __device__ __forceinline__ void lds2(ull &a, ull &b, unsigned addr) {
    asm volatile("ld.shared.v2.b64 {%0, %1}, [%2];" : "=l"(a), "=l"(b) : "r"(addr));
}
static __device__ __forceinline__ float2 unpack2(ull v) {
    float2 r; asm("mov.b64 {%0, %1}, %2;" : "=f"(r.x), "=f"(r.y) : "l"(v)); return r;
}

// =====================================================================
// K1: x(M x 128) @ [W_in | W_gate | W_lambda](128 x 640)  + bias + act
//     BM=128, BN=64, K=128. 256 threads, 8x4 microtile, FFMA2.
//     smem = A 64KB + B 32KB = 96KB  ->  2 CTAs per SM.
// =====================================================================
#define K1_SMEM 98304

__global__ void __launch_bounds__(256, 2)
k1_in_gemm(const float* __restrict__ x,
           const float* __restrict__ Win, const float* __restrict__ bin,
           const float* __restrict__ Wl,  const float* __restrict__ bl,
           const float* __restrict__ Wg,  const float* __restrict__ bg)
{
    extern __shared__ float sm[];
    float* As = sm;              // [128 m][128 k]
    float* Bs = sm + 128 * 128;  // [128 k][64 n]

    const int tid = threadIdx.x;
    const int nt = blockIdx.x;               // 0..9 (64-col tile)
    const int m0 = blockIdx.y * 128;

    // region select (uniform per block)
    const float* Wsrc; const float* bias; int ldn, c0;
    if (nt < 4)      { Wsrc = Win; bias = bin; ldn = 256; c0 = nt * 64; }
    else if (nt < 8) { Wsrc = Wg;  bias = bg;  ldn = 256; c0 = (nt - 4) * 64; }
    else             { Wsrc = Wl;  bias = bl;  ldn = 128; c0 = (nt - 8) * 64; }

    // ---- load A tile (coalesced float4)
    {
        const float4* xr = (const float4*)(x + (size_t)m0 * 128);
        float4* As4 = (float4*)As;
#pragma unroll
        for (int t = 0; t < 16; t++) As4[tid + t * 256] = xr[tid + t * 256];
    }
    // ---- load B tile (128 k x 64 n)
    {
        float4* Bs4 = (float4*)Bs;
#pragma unroll
        for (int t = 0; t < 8; t++) {
            int idx = tid + t * 256;          // 2048 float4
            int k = idx >> 4, n4 = idx & 15;
            Bs4[idx] = *(const float4*)&Wsrc[k * ldn + c0 + n4 * 4];
        }
    }
    __syncthreads();

    const int ty = tid >> 4;     // 0..15 -> rows ty*8
    const int tx = tid & 15;     // 0..15 -> cols tx*4
    const unsigned bs_base = (unsigned)__cvta_generic_to_shared(Bs) + tx * 16;
    const float4* As4c = (const float4*)As;

    ull acc[8][2];
#pragma unroll
    for (int i = 0; i < 8; i++) { acc[i][0] = 0ULL; acc[i][1] = 0ULL; }

#pragma unroll 4
    for (int kc = 0; kc < 32; kc++) {
        ull b[4][2];
#pragma unroll
        for (int kk = 0; kk < 4; kk++)
            lds2(b[kk][0], b[kk][1], bs_base + (unsigned)((kc * 4 + kk) * 256));
#pragma unroll
        for (int i = 0; i < 8; i++) {
            float4 a = As4c[(ty * 8 + i) * 32 + kc];
            ull a0 = pack2(a.x), a1 = pack2(a.y), a2 = pack2(a.z), a3 = pack2(a.w);
            ffma2(acc[i][0], a0, b[0][0]); ffma2(acc[i][1], a0, b[0][1]);
            ffma2(acc[i][0], a1, b[1][0]); ffma2(acc[i][1], a1, b[1][1]);
            ffma2(acc[i][0], a2, b[2][0]); ffma2(acc[i][1], a2, b[2][1]);
            ffma2(acc[i][0], a3, b[3][0]); ffma2(acc[i][1], a3, b[3][1]);
        }
    }

    // ---- epilogue: 4 cols per thread, float4 stores
    {
        const int nb = tx * 4;
        float4 b4 = *(const float4*)&bias[c0 + nb];
#pragma unroll
        for (int i = 0; i < 8; i++) {
            int row = m0 + ty * 8 + i;
            float v[4];
            float2 u0 = unpack2(acc[i][0]); v[0] = u0.x + b4.x; v[1] = u0.y + b4.y;
            float2 u1 = unpack2(acc[i][1]); v[2] = u1.x + b4.z; v[3] = u1.y + b4.w;
            float* dst;
            if (nt < 8) {
#pragma unroll
                for (int j = 0; j < 4; j++) v[j] = v[j] * sigmoidf_(v[j]);   // silu
                dst = (nt < 4 ? g_inp : g_gate) + (size_t)row * 256 + c0 + nb;
            } else {
#pragma unroll
                for (int j = 0; j < 4; j++) v[j] = sigmoidf_(v[j]);          // lambda
                dst = g_lam + (size_t)row * 128 + c0 + nb;
            }
            *(float4*)dst = make_float4(v[0], v[1], v[2], v[3]);
        }
    }
}

// =====================================================================
// K2: scans along H (axis 0). fwd(theta_f) writes acc; rev(theta_r) RMW.
// (round-4 version, known good)
// =====================================================================
__global__ void k2_hscan(const float* __restrict__ thf, const float* __restrict__ thr_)
{
    int idx = blockIdx.x * blockDim.x + threadIdx.x;
    int d  = idx & 127;
    int wb = idx >> 7;
    int base = wb * 128 + d;

    const float2* __restrict__ inp2 = (const float2*)g_inp;

    {
        float t = thf[d];
        float cf = cosf(t), sf = sinf(t);
        float hr = 0.f, hi = 0.f;
        int off = base;
#pragma unroll 4
        for (int h = 0; h < 128; h++, off += 131072) {
            float lam = g_lam[off];
            float2 p  = inp2[off];
            float a = lam * cf, b = lam * sf, om = 1.f - lam;
            float nr = a * hr - b * hi + om * p.x;
            float ni = a * hi + b * hr + om * p.y;
            hr = nr; hi = ni;
            g_acc[off] = make_float2(hr, hi);
        }
    }
    {
        float t = thr_[d];
        float cr = cosf(t), sr = sinf(t);
        float hr = 0.f, hi = 0.f;
        int off = base + 127 * 131072;
#pragma unroll 4
        for (int h = 0; h < 128; h++, off -= 131072) {
            float lam = g_lam[off];
            float2 p  = inp2[off];
            float a = lam * cr, b = lam * sr, om = 1.f - lam;
            float nr = a * hr - b * hi + om * p.x;
            float ni = a * hi + b * hr + om * p.y;
            hr = nr; hi = ni;
            float2 acc = g_acc[off];
            acc.x += hr; acc.y += hi;
            g_acc[off] = acc;
        }
    }
}

// =====================================================================
// K3: scans along W (axis 1). Both directions RMW into acc.
// (round-4 version, known good)
// =====================================================================
__global__ void k3_wscan(const float* __restrict__ thf, const float* __restrict__ thr_)
{
    int idx = blockIdx.x * blockDim.x + threadIdx.x;
    int d = idx & 127;
    int b = (idx >> 7) & 7;
    int h = idx >> 10;
    int base = (h * 1024 + b) * 128 + d;

    const float2* __restrict__ inp2 = (const float2*)g_inp;

    {
        float t = thf[d];
        float cf = cosf(t), sf = sinf(t);
        float hr = 0.f, hi = 0.f;
        int off = base;
#pragma unroll 4
        for (int w = 0; w < 128; w++, off += 1024) {
            float lam = g_lam[off];
            float2 p  = inp2[off];
            float a = lam * cf, bb = lam * sf, om = 1.f - lam;
            float nr = a * hr - bb * hi + om * p.x;
            float ni = a * hi + bb * hr + om * p.y;
            hr = nr; hi = ni;
            float2 acc = g_acc[off];
            acc.x += hr; acc.y += hi;
            g_acc[off] = acc;
        }
    }
    {
        float t = thr_[d];
        float cr = cosf(t), sr = sinf(t);
        float hr = 0.f, hi = 0.f;
        int off = base + 127 * 1024;
#pragma unroll 4
        for (int w = 0; w < 128; w++, off -= 1024) {
            float lam = g_lam[off];
            float2 p  = inp2[off];
            float a = lam * cr, bb = lam * sr, om = 1.f - lam;
            float nr = a * hr - bb * hi + om * p.x;
            float ni = a * hi + bb * hr + om * p.y;
            hr = nr; hi = ni;
            float2 acc = g_acc[off];
            acc.x += hr; acc.y += hi;
            g_acc[off] = acc;
        }
    }
}

// =====================================================================
// K4: LN(256)*ln_w+ln_b, *gate -> feat smem; GEMM @ W_out + b_out.
//     512 threads (16 warps), 4x4 microtile, FFMA2.  (round-8, 277 us)
// =====================================================================
#define FLD 260

__global__ void __launch_bounds__(512, 1)
k4_out_gemm(const float* __restrict__ Wout, const float* __restrict__ bout,
            const float* __restrict__ lnw,  const float* __restrict__ lnb,
            float* __restrict__ out)
{
    extern __shared__ float smf[];
    float* feat = smf;              // [64][FLD]
    float* Ws   = smf + 64 * FLD;   // [256][128]

    const int tid = threadIdx.x;
    const int m0 = blockIdx.x * 64;

    // ---- load W_out (256x128)
    {
        float4* Ws4 = (float4*)Ws;
        const float4* W4 = (const float4*)Wout;
#pragma unroll
        for (int t = 0; t < 16; t++) Ws4[tid + t * 512] = W4[tid + t * 512];
    }

    // ---- producer: LN stats + normalized, gated feature (8 lanes/row)
    {
        int r = tid >> 3;          // local row 0..63
        int q = tid & 7;           // 8 lanes cooperate per row
        int row = m0 + r;
        const float2* accp = g_acc + (size_t)row * 128;

        float sum = 0.f, ss = 0.f;
#pragma unroll
        for (int t = 0; t < 16; t++) {
            int dd = q + t * 8;
            float2 v = accp[dd];
            sum += v.x + v.y;
            ss  += v.x * v.x + v.y * v.y;
        }
        sum += __shfl_xor_sync(0xffffffffu, sum, 1);
        sum += __shfl_xor_sync(0xffffffffu, sum, 2);
        sum += __shfl_xor_sync(0xffffffffu, sum, 4);
        ss  += __shfl_xor_sync(0xffffffffu, ss, 1);
        ss  += __shfl_xor_sync(0xffffffffu, ss, 2);
        ss  += __shfl_xor_sync(0xffffffffu, ss, 4);

        float mu   = sum * (1.0f / 256.0f);
        float var  = ss * (1.0f / 256.0f) - mu * mu;
        float rstd = rsqrtf(var + 1e-5f);

        const float* gr = g_gate + (size_t)row * 256;
#pragma unroll
        for (int t = 0; t < 16; t++) {
            int dd = q + t * 8;
            float2 v = accp[dd];
            float fr = ((v.x - mu) * rstd * lnw[dd]       + lnb[dd])       * gr[dd];
            float fi = ((v.y - mu) * rstd * lnw[128 + dd] + lnb[128 + dd]) * gr[128 + dd];
            feat[r * FLD + dd]       = fr;
            feat[r * FLD + 128 + dd] = fi;
        }
    }
    __syncthreads();

    // ---- GEMM: feat(64x256) @ Ws(256x128); 16(ty) x 32(tx), 4x4 microtile
    const int ty = tid >> 5;     // rows ty*4
    const int tx = tid & 31;     // cols tx*4
    const unsigned ws_base = (unsigned)__cvta_generic_to_shared(Ws) + tx * 16;

    ull acc[4][2];
#pragma unroll
    for (int i = 0; i < 4; i++) { acc[i][0] = 0ULL; acc[i][1] = 0ULL; }

#pragma unroll 4
    for (int kc = 0; kc < 64; kc++) {
        ull b[4][2];
#pragma unroll
        for (int kk = 0; kk < 4; kk++)
            lds2(b[kk][0], b[kk][1], ws_base + (unsigned)((kc * 4 + kk) * 512));
#pragma unroll
        for (int i = 0; i < 4; i++) {
            float4 a = *(const float4*)&feat[(ty * 4 + i) * FLD + kc * 4];
            ull a0 = pack2(a.x), a1 = pack2(a.y), a2 = pack2(a.z), a3 = pack2(a.w);
            ffma2(acc[i][0], a0, b[0][0]); ffma2(acc[i][1], a0, b[0][1]);
            ffma2(acc[i][0], a1, b[1][0]); ffma2(acc[i][1], a1, b[1][1]);
            ffma2(acc[i][0], a2, b[2][0]); ffma2(acc[i][1], a2, b[2][1]);
            ffma2(acc[i][0], a3, b[3][0]); ffma2(acc[i][1], a3, b[3][1]);
        }
    }

    // ---- epilogue: 4 cols per thread, float4 stores
    {
        float4 b4 = *(const float4*)&bout[tx * 4];
#pragma unroll
        for (int i = 0; i < 4; i++) {
            int row = m0 + ty * 4 + i;
            float2 u0 = unpack2(acc[i][0]);
            float2 u1 = unpack2(acc[i][1]);
            float* dst = out + (size_t)row * 128 + tx * 4;
            *(float4*)dst = make_float4(u0.x + b4.x, u0.y + b4.y,
                                        u1.x + b4.z, u1.y + b4.w);
        }
    }
}

// =====================================================================
extern "C" void kernel_launch(void* const* d_in, const int* in_sizes, int n_in,
                              void* d_out, int out_size)
{
    const float* x    = (const float*)d_in[0];
    const float* Win  = (const float*)d_in[1];
    const float* bin  = (const float*)d_in[2];
    const float* Wl   = (const float*)d_in[3];
    const float* bl   = (const float*)d_in[4];
    const float* thf  = (const float*)d_in[5];
    const float* thr_ = (const float*)d_in[6];
    const float* Wg   = (const float*)d_in[7];
    const float* bg   = (const float*)d_in[8];
    const float* Wout = (const float*)d_in[9];
    const float* bout = (const float*)d_in[10];
    const float* lnw  = (const float*)d_in[11];
    const float* lnb  = (const float*)d_in[12];
    float* out = (float*)d_out;

    const int SM4 = (64 * FLD + 256 * 128) * 4;        // 197632
    cudaFuncSetAttribute(k1_in_gemm,  cudaFuncAttributeMaxDynamicSharedMemorySize, K1_SMEM);
    cudaFuncSetAttribute(k4_out_gemm, cudaFuncAttributeMaxDynamicSharedMemorySize, SM4);

    dim3 g1(10, MM / 128);                             // (10, 1024)
    k1_in_gemm<<<g1, 256, K1_SMEM>>>(x, Win, bin, Wl, bl, Wg, bg);

    k2_hscan<<<MM / 256, 256>>>(thf, thr_);
    k3_wscan<<<MM / 256, 256>>>(thf, thr_);

    k4_out_gemm<<<MM / 64, 512, SM4>>>(Wout, bout, lnw, lnb, out);
}

// round 10
// speedup vs baseline: 1.6622x; 1.0190x over previous
#include <cuda_runtime.h>
#include <math.h>
#include <stdint.h>

// Problem dims
#define HH 128
#define WW 128
#define BB 8
#define DD 128
#define MM (HH*WW*BB)          // 131072 rows

typedef unsigned long long ull;

// ---------------- scratch (no cudaMalloc allowed) ----------------
__device__ float  g_inp [MM * 256];   // silu(x@W_in + b_in), interleaved re/im
__device__ float  g_gate[MM * 256];   // silu(x@W_gate + b_gate)
__device__ float  g_lam [MM * 128];   // sigmoid(x@W_lambda + b_lambda)
__device__ float2 g_acc [MM * 128];   // sum of 4 scans

static __device__ __forceinline__ float sigmoidf_(float v) {
    return 1.0f / (1.0f + expf(-v));
}

// ---------------- packed fp32x2 helpers ----------------
static __device__ __forceinline__ ull pack2(float v) {
    ull r; asm("mov.b64 %0, {%1, %1};" : "=l"(r) : "f"(v)); return r;
}
static __device__ __forceinline__ void ffma2(ull &d, ull a, ull b) {
    asm("fma.rn.f32x2 %0, %1, %2, %0;" : "+l"(d) : "l"(a), "l"(b));
}
static __device__ __forceinline__ void lds2(ull &a, ull &b, unsigned addr) {
    asm volatile("ld.shared.v2.b64 {%0, %1}, [%2];" : "=l"(a), "=l"(b) : "r"(addr));
}
static __device__ __forceinline__ float2 unpack2(ull v) {
    float2 r; asm("mov.b64 {%0, %1}, %2;" : "=f"(r.x), "=f"(r.y) : "l"(v)); return r;
}

// =====================================================================
// K1: x(M x 128) @ [W_in | W_gate | W_lambda](128 x 640)  + bias + act
//     BM=128, BN=64, K=128. 256 threads, 8x4 microtile, FFMA2.
//     smem = A 64KB + B 32KB = 96KB  ->  2 CTAs per SM.   (round-9)
// =====================================================================
#define K1_SMEM 98304

__global__ void __launch_bounds__(256, 2)
k1_in_gemm(const float* __restrict__ x,
           const float* __restrict__ Win, const float* __restrict__ bin,
           const float* __restrict__ Wl,  const float* __restrict__ bl,
           const float* __restrict__ Wg,  const float* __restrict__ bg)
{
    extern __shared__ float sm[];
    float* As = sm;              // [128 m][128 k]
    float* Bs = sm + 128 * 128;  // [128 k][64 n]

    const int tid = threadIdx.x;
    const int nt = blockIdx.x;               // 0..9 (64-col tile)
    const int m0 = blockIdx.y * 128;

    const float* Wsrc; const float* bias; int ldn, c0;
    if (nt < 4)      { Wsrc = Win; bias = bin; ldn = 256; c0 = nt * 64; }
    else if (nt < 8) { Wsrc = Wg;  bias = bg;  ldn = 256; c0 = (nt - 4) * 64; }
    else             { Wsrc = Wl;  bias = bl;  ldn = 128; c0 = (nt - 8) * 64; }

    {
        const float4* xr = (const float4*)(x + (size_t)m0 * 128);
        float4* As4 = (float4*)As;
#pragma unroll
        for (int t = 0; t < 16; t++) As4[tid + t * 256] = xr[tid + t * 256];
    }
    {
        float4* Bs4 = (float4*)Bs;
#pragma unroll
        for (int t = 0; t < 8; t++) {
            int idx = tid + t * 256;
            int k = idx >> 4, n4 = idx & 15;
            Bs4[idx] = *(const float4*)&Wsrc[k * ldn + c0 + n4 * 4];
        }
    }
    __syncthreads();

    const int ty = tid >> 4;     // 0..15 -> rows ty*8
    const int tx = tid & 15;     // 0..15 -> cols tx*4
    const unsigned bs_base = (unsigned)__cvta_generic_to_shared(Bs) + tx * 16;
    const float4* As4c = (const float4*)As;

    ull acc[8][2];
#pragma unroll
    for (int i = 0; i < 8; i++) { acc[i][0] = 0ULL; acc[i][1] = 0ULL; }

#pragma unroll 4
    for (int kc = 0; kc < 32; kc++) {
        ull b[4][2];
#pragma unroll
        for (int kk = 0; kk < 4; kk++)
            lds2(b[kk][0], b[kk][1], bs_base + (unsigned)((kc * 4 + kk) * 256));
#pragma unroll
        for (int i = 0; i < 8; i++) {
            float4 a = As4c[(ty * 8 + i) * 32 + kc];
            ull a0 = pack2(a.x), a1 = pack2(a.y), a2 = pack2(a.z), a3 = pack2(a.w);
            ffma2(acc[i][0], a0, b[0][0]); ffma2(acc[i][1], a0, b[0][1]);
            ffma2(acc[i][0], a1, b[1][0]); ffma2(acc[i][1], a1, b[1][1]);
            ffma2(acc[i][0], a2, b[2][0]); ffma2(acc[i][1], a2, b[2][1]);
            ffma2(acc[i][0], a3, b[3][0]); ffma2(acc[i][1], a3, b[3][1]);
        }
    }

    {
        const int nb = tx * 4;
        float4 b4 = *(const float4*)&bias[c0 + nb];
#pragma unroll
        for (int i = 0; i < 8; i++) {
            int row = m0 + ty * 8 + i;
            float v[4];
            float2 u0 = unpack2(acc[i][0]); v[0] = u0.x + b4.x; v[1] = u0.y + b4.y;
            float2 u1 = unpack2(acc[i][1]); v[2] = u1.x + b4.z; v[3] = u1.y + b4.w;
            float* dst;
            if (nt < 8) {
#pragma unroll
                for (int j = 0; j < 4; j++) v[j] = v[j] * sigmoidf_(v[j]);   // silu
                dst = (nt < 4 ? g_inp : g_gate) + (size_t)row * 256 + c0 + nb;
            } else {
#pragma unroll
                for (int j = 0; j < 4; j++) v[j] = sigmoidf_(v[j]);          // lambda
                dst = g_lam + (size_t)row * 128 + c0 + nb;
            }
            *(float4*)dst = make_float4(v[0], v[1], v[2], v[3]);
        }
    }
}

// =====================================================================
// K2: scans along H (axis 0). fwd(theta_f) writes acc; rev(theta_r) RMW.
// =====================================================================
__global__ void k2_hscan(const float* __restrict__ thf, const float* __restrict__ thr_)
{
    int idx = blockIdx.x * blockDim.x + threadIdx.x;
    int d  = idx & 127;
    int wb = idx >> 7;
    int base = wb * 128 + d;

    const float2* __restrict__ inp2 = (const float2*)g_inp;

    {
        float t = thf[d];
        float cf = cosf(t), sf = sinf(t);
        float hr = 0.f, hi = 0.f;
        int off = base;
#pragma unroll 8
        for (int h = 0; h < 128; h++, off += 131072) {
            float lam = g_lam[off];
            float2 p  = inp2[off];
            float a = lam * cf, b = lam * sf, om = 1.f - lam;
            float nr = a * hr - b * hi + om * p.x;
            float ni = a * hi + b * hr + om * p.y;
            hr = nr; hi = ni;
            g_acc[off] = make_float2(hr, hi);
        }
    }
    {
        float t = thr_[d];
        float cr = cosf(t), sr = sinf(t);
        float hr = 0.f, hi = 0.f;
        int off = base + 127 * 131072;
#pragma unroll 8
        for (int h = 0; h < 128; h++, off -= 131072) {
            float lam = g_lam[off];
            float2 p  = inp2[off];
            float a = lam * cr, b = lam * sr, om = 1.f - lam;
            float nr = a * hr - b * hi + om * p.x;
            float ni = a * hi + b * hr + om * p.y;
            hr = nr; hi = ni;
            float2 acc = g_acc[off];
            acc.x += hr; acc.y += hi;
            g_acc[off] = acc;
        }
    }
}

// =====================================================================
// K3: scans along W (axis 1). Both directions RMW into acc.
// =====================================================================
__global__ void k3_wscan(const float* __restrict__ thf, const float* __restrict__ thr_)
{
    int idx = blockIdx.x * blockDim.x + threadIdx.x;
    int d = idx & 127;
    int b = (idx >> 7) & 7;
    int h = idx >> 10;
    int base = (h * 1024 + b) * 128 + d;

    const float2* __restrict__ inp2 = (const float2*)g_inp;

    {
        float t = thf[d];
        float cf = cosf(t), sf = sinf(t);
        float hr = 0.f, hi = 0.f;
        int off = base;
#pragma unroll 8
        for (int w = 0; w < 128; w++, off += 1024) {
            float lam = g_lam[off];
            float2 p  = inp2[off];
            float a = lam * cf, bb = lam * sf, om = 1.f - lam;
            float nr = a * hr - bb * hi + om * p.x;
            float ni = a * hi + bb * hr + om * p.y;
            hr = nr; hi = ni;
            float2 acc = g_acc[off];
            acc.x += hr; acc.y += hi;
            g_acc[off] = acc;
        }
    }
    {
        float t = thr_[d];
        float cr = cosf(t), sr = sinf(t);
        float hr = 0.f, hi = 0.f;
        int off = base + 127 * 1024;
#pragma unroll 8
        for (int w = 0; w < 128; w++, off -= 1024) {
            float lam = g_lam[off];
            float2 p  = inp2[off];
            float a = lam * cr, bb = lam * sr, om = 1.f - lam;
            float nr = a * hr - bb * hi + om * p.x;
            float ni = a * hi + bb * hr + om * p.y;
            hr = nr; hi = ni;
            float2 acc = g_acc[off];
            acc.x += hr; acc.y += hi;
            g_acc[off] = acc;
        }
    }
}

// =====================================================================
// K4: LN(256)*ln_w+ln_b, *gate -> feat smem; GEMM @ W_out + b_out.
//     256 threads (8 warps), 8x4 microtile, FFMA2.
//     Warp = one 8-row group -> A loads are warp-broadcast (1 phase);
//     B LDS bytes per FFMA2 halved vs 4x4 tile.
// =====================================================================
#define FLD 260

__global__ void __launch_bounds__(256, 1)
k4_out_gemm(const float* __restrict__ Wout, const float* __restrict__ bout,
            const float* __restrict__ lnw,  const float* __restrict__ lnb,
            float* __restrict__ out)
{
    extern __shared__ float smf[];
    float* feat = smf;              // [64][FLD]
    float* Ws   = smf + 64 * FLD;   // [256][128]

    const int tid = threadIdx.x;
    const int m0 = blockIdx.x * 64;

    // ---- load W_out (256x128)
    {
        float4* Ws4 = (float4*)Ws;
        const float4* W4 = (const float4*)Wout;
#pragma unroll
        for (int t = 0; t < 32; t++) Ws4[tid + t * 256] = W4[tid + t * 256];
    }

    // ---- producer: LN stats + normalized, gated feature (4 lanes/row)
    {
        int r = tid >> 2;          // local row 0..63
        int q = tid & 3;           // 4 lanes cooperate per row
        int row = m0 + r;
        const float2* accp = g_acc + (size_t)row * 128;

        float sum = 0.f, ss = 0.f;
#pragma unroll
        for (int t = 0; t < 32; t++) {
            int dd = q + t * 4;
            float2 v = accp[dd];
            sum += v.x + v.y;
            ss  += v.x * v.x + v.y * v.y;
        }
        sum += __shfl_xor_sync(0xffffffffu, sum, 1);
        sum += __shfl_xor_sync(0xffffffffu, sum, 2);
        ss  += __shfl_xor_sync(0xffffffffu, ss, 1);
        ss  += __shfl_xor_sync(0xffffffffu, ss, 2);

        float mu   = sum * (1.0f / 256.0f);
        float var  = ss * (1.0f / 256.0f) - mu * mu;
        float rstd = rsqrtf(var + 1e-5f);

        const float* gr = g_gate + (size_t)row * 256;
#pragma unroll
        for (int t = 0; t < 32; t++) {
            int dd = q + t * 4;
            float2 v = accp[dd];
            float fr = ((v.x - mu) * rstd * lnw[dd]       + lnb[dd])       * gr[dd];
            float fi = ((v.y - mu) * rstd * lnw[128 + dd] + lnb[128 + dd]) * gr[128 + dd];
            feat[r * FLD + dd]       = fr;
            feat[r * FLD + 128 + dd] = fi;
        }
    }
    __syncthreads();

    // ---- GEMM: feat(64x256) @ Ws(256x128); 8(ty) x 32(tx), 8x4 microtile
    const int ty = tid >> 5;     // warp id 0..7 -> rows ty*8  (A = broadcast)
    const int tx = tid & 31;     // lane 0..31  -> cols tx*4
    const unsigned ws_base = (unsigned)__cvta_generic_to_shared(Ws) + tx * 16;

    ull acc[8][2];
#pragma unroll
    for (int i = 0; i < 8; i++) { acc[i][0] = 0ULL; acc[i][1] = 0ULL; }

#pragma unroll 4
    for (int kc = 0; kc < 64; kc++) {
        ull b[4][2];
#pragma unroll
        for (int kk = 0; kk < 4; kk++)
            lds2(b[kk][0], b[kk][1], ws_base + (unsigned)((kc * 4 + kk) * 512));
#pragma unroll
        for (int i = 0; i < 8; i++) {
            float4 a = *(const float4*)&feat[(ty * 8 + i) * FLD + kc * 4];
            ull a0 = pack2(a.x), a1 = pack2(a.y), a2 = pack2(a.z), a3 = pack2(a.w);
            ffma2(acc[i][0], a0, b[0][0]); ffma2(acc[i][1], a0, b[0][1]);
            ffma2(acc[i][0], a1, b[1][0]); ffma2(acc[i][1], a1, b[1][1]);
            ffma2(acc[i][0], a2, b[2][0]); ffma2(acc[i][1], a2, b[2][1]);
            ffma2(acc[i][0], a3, b[3][0]); ffma2(acc[i][1], a3, b[3][1]);
        }
    }

    // ---- epilogue: 4 cols per thread, float4 stores (coalesced per warp)
    {
        float4 b4 = *(const float4*)&bout[tx * 4];
#pragma unroll
        for (int i = 0; i < 8; i++) {
            int row = m0 + ty * 8 + i;
            float2 u0 = unpack2(acc[i][0]);
            float2 u1 = unpack2(acc[i][1]);
            float* dst = out + (size_t)row * 128 + tx * 4;
            *(float4*)dst = make_float4(u0.x + b4.x, u0.y + b4.y,
                                        u1.x + b4.z, u1.y + b4.w);
        }
    }
}

// =====================================================================
extern "C" void kernel_launch(void* const* d_in, const int* in_sizes, int n_in,
                              void* d_out, int out_size)
{
    const float* x    = (const float*)d_in[0];
    const float* Win  = (const float*)d_in[1];
    const float* bin  = (const float*)d_in[2];
    const float* Wl   = (const float*)d_in[3];
    const float* bl   = (const float*)d_in[4];
    const float* thf  = (const float*)d_in[5];
    const float* thr_ = (const float*)d_in[6];
    const float* Wg   = (const float*)d_in[7];
    const float* bg   = (const float*)d_in[8];
    const float* Wout = (const float*)d_in[9];
    const float* bout = (const float*)d_in[10];
    const float* lnw  = (const float*)d_in[11];
    const float* lnb  = (const float*)d_in[12];
    float* out = (float*)d_out;

    const int SM4 = (64 * FLD + 256 * 128) * 4;        // 197632
    cudaFuncSetAttribute(k1_in_gemm,  cudaFuncAttributeMaxDynamicSharedMemorySize, K1_SMEM);
    cudaFuncSetAttribute(k4_out_gemm, cudaFuncAttributeMaxDynamicSharedMemorySize, SM4);

    dim3 g1(10, MM / 128);                             // (10, 1024)
    k1_in_gemm<<<g1, 256, K1_SMEM>>>(x, Win, bin, Wl, bl, Wg, bg);

    k2_hscan<<<MM / 256, 256>>>(thf, thr_);
    k3_wscan<<<MM / 256, 256>>>(thf, thr_);

    k4_out_gemm<<<MM / 64, 256, SM4>>>(Wout, bout, lnw, lnb, out);
}

// round 11
// speedup vs baseline: 1.7129x; 1.0305x over previous
#include <cuda_runtime.h>
#include <math.h>
#include <stdint.h>

// Problem dims
#define HH 128
#define WW 128
#define BB 8
#define DD 128
#define MM (HH*WW*BB)          // 131072 rows

typedef unsigned long long ull;

// ---------------- scratch (no cudaMalloc allowed) ----------------
__device__ float  g_inp [MM * 256];   // silu(x@W_in + b_in), interleaved re/im
__device__ float  g_gate[MM * 256];   // silu(x@W_gate + b_gate)
__device__ float  g_lam [MM * 128];   // sigmoid(x@W_lambda + b_lambda)
__device__ float2 g_acc [MM * 128];   // sum of 4 scans

static __device__ __forceinline__ float sigmoidf_(float v) {
    return 1.0f / (1.0f + __expf(-v));     // MUFU path; ~2^-21 rel err
}

// ---------------- packed fp32x2 helpers ----------------
static __device__ __forceinline__ ull pack2(float v) {
    ull r; asm("mov.b64 %0, {%1, %1};" : "=l"(r) : "f"(v)); return r;
}
static __device__ __forceinline__ void ffma2(ull &d, ull a, ull b) {
    asm("fma.rn.f32x2 %0, %1, %2, %0;" : "+l"(d) : "l"(a), "l"(b));
}
static __device__ __forceinline__ void lds2(ull &a, ull &b, unsigned addr) {
    asm volatile("ld.shared.v2.b64 {%0, %1}, [%2];" : "=l"(a), "=l"(b) : "r"(addr));
}
static __device__ __forceinline__ float2 unpack2(ull v) {
    float2 r; asm("mov.b64 {%0, %1}, %2;" : "=f"(r.x), "=f"(r.y) : "l"(v)); return r;
}

// =====================================================================
// K1: x(M x 128) @ [W_in | W_gate | W_lambda](128 x 640)  + bias + act
//     BM=128, BN=64, K=128. 256 threads, 8x4 microtile, FFMA2.
//     smem = A 64KB + B 32KB = 96KB  ->  2 CTAs per SM.   (round-9)
// =====================================================================
#define K1_SMEM 98304

__global__ void __launch_bounds__(256, 2)
k1_in_gemm(const float* __restrict__ x,
           const float* __restrict__ Win, const float* __restrict__ bin,
           const float* __restrict__ Wl,  const float* __restrict__ bl,
           const float* __restrict__ Wg,  const float* __restrict__ bg)
{
    extern __shared__ float sm[];
    float* As = sm;              // [128 m][128 k]
    float* Bs = sm + 128 * 128;  // [128 k][64 n]

    const int tid = threadIdx.x;
    const int nt = blockIdx.x;               // 0..9 (64-col tile)
    const int m0 = blockIdx.y * 128;

    const float* Wsrc; const float* bias; int ldn, c0;
    if (nt < 4)      { Wsrc = Win; bias = bin; ldn = 256; c0 = nt * 64; }
    else if (nt < 8) { Wsrc = Wg;  bias = bg;  ldn = 256; c0 = (nt - 4) * 64; }
    else             { Wsrc = Wl;  bias = bl;  ldn = 128; c0 = (nt - 8) * 64; }

    {
        const float4* xr = (const float4*)(x + (size_t)m0 * 128);
        float4* As4 = (float4*)As;
#pragma unroll
        for (int t = 0; t < 16; t++) As4[tid + t * 256] = xr[tid + t * 256];
    }
    {
        float4* Bs4 = (float4*)Bs;
#pragma unroll
        for (int t = 0; t < 8; t++) {
            int idx = tid + t * 256;
            int k = idx >> 4, n4 = idx & 15;
            Bs4[idx] = *(const float4*)&Wsrc[k * ldn + c0 + n4 * 4];
        }
    }
    __syncthreads();

    const int ty = tid >> 4;     // 0..15 -> rows ty*8
    const int tx = tid & 15;     // 0..15 -> cols tx*4
    const unsigned bs_base = (unsigned)__cvta_generic_to_shared(Bs) + tx * 16;
    const float4* As4c = (const float4*)As;

    ull acc[8][2];
#pragma unroll
    for (int i = 0; i < 8; i++) { acc[i][0] = 0ULL; acc[i][1] = 0ULL; }

#pragma unroll 4
    for (int kc = 0; kc < 32; kc++) {
        ull b[4][2];
#pragma unroll
        for (int kk = 0; kk < 4; kk++)
            lds2(b[kk][0], b[kk][1], bs_base + (unsigned)((kc * 4 + kk) * 256));
#pragma unroll
        for (int i = 0; i < 8; i++) {
            float4 a = As4c[(ty * 8 + i) * 32 + kc];
            ull a0 = pack2(a.x), a1 = pack2(a.y), a2 = pack2(a.z), a3 = pack2(a.w);
            ffma2(acc[i][0], a0, b[0][0]); ffma2(acc[i][1], a0, b[0][1]);
            ffma2(acc[i][0], a1, b[1][0]); ffma2(acc[i][1], a1, b[1][1]);
            ffma2(acc[i][0], a2, b[2][0]); ffma2(acc[i][1], a2, b[2][1]);
            ffma2(acc[i][0], a3, b[3][0]); ffma2(acc[i][1], a3, b[3][1]);
        }
    }

    {
        const int nb = tx * 4;
        float4 b4 = *(const float4*)&bias[c0 + nb];
#pragma unroll
        for (int i = 0; i < 8; i++) {
            int row = m0 + ty * 8 + i;
            float v[4];
            float2 u0 = unpack2(acc[i][0]); v[0] = u0.x + b4.x; v[1] = u0.y + b4.y;
            float2 u1 = unpack2(acc[i][1]); v[2] = u1.x + b4.z; v[3] = u1.y + b4.w;
            float* dst;
            if (nt < 8) {
#pragma unroll
                for (int j = 0; j < 4; j++) v[j] = v[j] * sigmoidf_(v[j]);   // silu
                dst = (nt < 4 ? g_inp : g_gate) + (size_t)row * 256 + c0 + nb;
            } else {
#pragma unroll
                for (int j = 0; j < 4; j++) v[j] = sigmoidf_(v[j]);          // lambda
                dst = g_lam + (size_t)row * 128 + c0 + nb;
            }
            *(float4*)dst = make_float4(v[0], v[1], v[2], v[3]);
        }
    }
}

// =====================================================================
// K2: scans along H (axis 0). fwd(theta_f) writes acc; rev(theta_r) RMW.
// =====================================================================
__global__ void k2_hscan(const float* __restrict__ thf, const float* __restrict__ thr_)
{
    int idx = blockIdx.x * blockDim.x + threadIdx.x;
    int d  = idx & 127;
    int wb = idx >> 7;
    int base = wb * 128 + d;

    const float2* __restrict__ inp2 = (const float2*)g_inp;

    {
        float t = thf[d];
        float cf = cosf(t), sf = sinf(t);
        float hr = 0.f, hi = 0.f;
        int off = base;
#pragma unroll 8
        for (int h = 0; h < 128; h++, off += 131072) {
            float lam = g_lam[off];
            float2 p  = inp2[off];
            float a = lam * cf, b = lam * sf, om = 1.f - lam;
            float nr = a * hr - b * hi + om * p.x;
            float ni = a * hi + b * hr + om * p.y;
            hr = nr; hi = ni;
            g_acc[off] = make_float2(hr, hi);
        }
    }
    {
        float t = thr_[d];
        float cr = cosf(t), sr = sinf(t);
        float hr = 0.f, hi = 0.f;
        int off = base + 127 * 131072;
#pragma unroll 8
        for (int h = 0; h < 128; h++, off -= 131072) {
            float lam = g_lam[off];
            float2 p  = inp2[off];
            float a = lam * cr, b = lam * sr, om = 1.f - lam;
            float nr = a * hr - b * hi + om * p.x;
            float ni = a * hi + b * hr + om * p.y;
            hr = nr; hi = ni;
            float2 acc = g_acc[off];
            acc.x += hr; acc.y += hi;
            g_acc[off] = acc;
        }
    }
}

// =====================================================================
// K3: scans along W (axis 1). Both directions RMW into acc.
// =====================================================================
__global__ void k3_wscan(const float* __restrict__ thf, const float* __restrict__ thr_)
{
    int idx = blockIdx.x * blockDim.x + threadIdx.x;
    int d = idx & 127;
    int b = (idx >> 7) & 7;
    int h = idx >> 10;
    int base = (h * 1024 + b) * 128 + d;

    const float2* __restrict__ inp2 = (const float2*)g_inp;

    {
        float t = thf[d];
        float cf = cosf(t), sf = sinf(t);
        float hr = 0.f, hi = 0.f;
        int off = base;
#pragma unroll 8
        for (int w = 0; w < 128; w++, off += 1024) {
            float lam = g_lam[off];
            float2 p  = inp2[off];
            float a = lam * cf, bb = lam * sf, om = 1.f - lam;
            float nr = a * hr - bb * hi + om * p.x;
            float ni = a * hi + bb * hr + om * p.y;
            hr = nr; hi = ni;
            float2 acc = g_acc[off];
            acc.x += hr; acc.y += hi;
            g_acc[off] = acc;
        }
    }
    {
        float t = thr_[d];
        float cr = cosf(t), sr = sinf(t);
        float hr = 0.f, hi = 0.f;
        int off = base + 127 * 1024;
#pragma unroll 8
        for (int w = 0; w < 128; w++, off -= 1024) {
            float lam = g_lam[off];
            float2 p  = inp2[off];
            float a = lam * cr, bb = lam * sr, om = 1.f - lam;
            float nr = a * hr - bb * hi + om * p.x;
            float ni = a * hi + bb * hr + om * p.y;
            hr = nr; hi = ni;
            float2 acc = g_acc[off];
            acc.x += hr; acc.y += hi;
            g_acc[off] = acc;
        }
    }
}

// =====================================================================
// K4: LN(256)*ln_w+ln_b, *gate -> feat smem; GEMM @ W_out + b_out.
//     512 threads (16 warps), 2-way split-K, 8x4 microtile, FFMA2.
//     Group g (256 thr) does kc in [g*32, g*32+32); warp = 8-row group
//     (A broadcast). Group 1 stages partials; group 0 merges + stores.
// =====================================================================
#define FLD 260
#define STG 132

__global__ void __launch_bounds__(512, 1)
k4_out_gemm(const float* __restrict__ Wout, const float* __restrict__ bout,
            const float* __restrict__ lnw,  const float* __restrict__ lnb,
            float* __restrict__ out)
{
    extern __shared__ float smf[];
    float* feat = smf;              // [64][FLD]
    float* Ws   = smf + 64 * FLD;   // [256][128]

    const int tid = threadIdx.x;
    const int m0 = blockIdx.x * 64;

    // ---- load W_out (256x128)
    {
        float4* Ws4 = (float4*)Ws;
        const float4* W4 = (const float4*)Wout;
#pragma unroll
        for (int t = 0; t < 16; t++) Ws4[tid + t * 512] = W4[tid + t * 512];
    }

    // ---- producer: LN stats + normalized, gated feature (8 lanes/row)
    {
        int r = tid >> 3;          // local row 0..63
        int q = tid & 7;           // 8 lanes cooperate per row
        int row = m0 + r;
        const float2* accp = g_acc + (size_t)row * 128;

        float sum = 0.f, ss = 0.f;
#pragma unroll
        for (int t = 0; t < 16; t++) {
            int dd = q + t * 8;
            float2 v = accp[dd];
            sum += v.x + v.y;
            ss  += v.x * v.x + v.y * v.y;
        }
        sum += __shfl_xor_sync(0xffffffffu, sum, 1);
        sum += __shfl_xor_sync(0xffffffffu, sum, 2);
        sum += __shfl_xor_sync(0xffffffffu, sum, 4);
        ss  += __shfl_xor_sync(0xffffffffu, ss, 1);
        ss  += __shfl_xor_sync(0xffffffffu, ss, 2);
        ss  += __shfl_xor_sync(0xffffffffu, ss, 4);

        float mu   = sum * (1.0f / 256.0f);
        float var  = ss * (1.0f / 256.0f) - mu * mu;
        float rstd = rsqrtf(var + 1e-5f);

        const float* gr = g_gate + (size_t)row * 256;
#pragma unroll
        for (int t = 0; t < 16; t++) {
            int dd = q + t * 8;
            float2 v = accp[dd];
            float fr = ((v.x - mu) * rstd * lnw[dd]       + lnb[dd])       * gr[dd];
            float fi = ((v.y - mu) * rstd * lnw[128 + dd] + lnb[128 + dd]) * gr[128 + dd];
            feat[r * FLD + dd]       = fr;
            feat[r * FLD + 128 + dd] = fi;
        }
    }
    __syncthreads();

    // ---- GEMM: split-K. group = tid>>8; within group: 8(ty warp) x 32(tx lane)
    const int gid = tid >> 8;
    const int lt  = tid & 255;
    const int ty  = lt >> 5;     // warp-in-group 0..7 -> rows ty*8 (A broadcast)
    const int tx  = lt & 31;     // cols tx*4
    const unsigned ws_base = (unsigned)__cvta_generic_to_shared(Ws) + tx * 16;

    ull acc[8][2];
#pragma unroll
    for (int i = 0; i < 8; i++) { acc[i][0] = 0ULL; acc[i][1] = 0ULL; }

    const int kc0 = gid * 32;
#pragma unroll 4
    for (int kq = 0; kq < 32; kq++) {
        const int kc = kc0 + kq;
        ull b[4][2];
#pragma unroll
        for (int kk = 0; kk < 4; kk++)
            lds2(b[kk][0], b[kk][1], ws_base + (unsigned)((kc * 4 + kk) * 512));
#pragma unroll
        for (int i = 0; i < 8; i++) {
            float4 a = *(const float4*)&feat[(ty * 8 + i) * FLD + kc * 4];
            ull a0 = pack2(a.x), a1 = pack2(a.y), a2 = pack2(a.z), a3 = pack2(a.w);
            ffma2(acc[i][0], a0, b[0][0]); ffma2(acc[i][1], a0, b[0][1]);
            ffma2(acc[i][0], a1, b[1][0]); ffma2(acc[i][1], a1, b[1][1]);
            ffma2(acc[i][0], a2, b[2][0]); ffma2(acc[i][1], a2, b[2][1]);
            ffma2(acc[i][0], a3, b[3][0]); ffma2(acc[i][1], a3, b[3][1]);
        }
    }
    __syncthreads();   // feat dead; reuse as stage [64][STG]

    float* stage = smf;
    if (gid == 1) {
#pragma unroll
        for (int i = 0; i < 8; i++) {
            float2 u0 = unpack2(acc[i][0]);
            float2 u1 = unpack2(acc[i][1]);
            *(float4*)&stage[(ty * 8 + i) * STG + tx * 4] =
                make_float4(u0.x, u0.y, u1.x, u1.y);
        }
    }
    __syncthreads();

    if (gid == 0) {
        float4 b4 = *(const float4*)&bout[tx * 4];
#pragma unroll
        for (int i = 0; i < 8; i++) {
            int row = m0 + ty * 8 + i;
            float4 s = *(const float4*)&stage[(ty * 8 + i) * STG + tx * 4];
            float2 u0 = unpack2(acc[i][0]);
            float2 u1 = unpack2(acc[i][1]);
            float* dst = out + (size_t)row * 128 + tx * 4;
            *(float4*)dst = make_float4(u0.x + s.x + b4.x, u0.y + s.y + b4.y,
                                        u1.x + s.z + b4.z, u1.y + s.w + b4.w);
        }
    }
}

// =====================================================================
extern "C" void kernel_launch(void* const* d_in, const int* in_sizes, int n_in,
                              void* d_out, int out_size)
{
    const float* x    = (const float*)d_in[0];
    const float* Win  = (const float*)d_in[1];
    const float* bin  = (const float*)d_in[2];
    const float* Wl   = (const float*)d_in[3];
    const float* bl   = (const float*)d_in[4];
    const float* thf  = (const float*)d_in[5];
    const float* thr_ = (const float*)d_in[6];
    const float* Wg   = (const float*)d_in[7];
    const float* bg   = (const float*)d_in[8];
    const float* Wout = (const float*)d_in[9];
    const float* bout = (const float*)d_in[10];
    const float* lnw  = (const float*)d_in[11];
    const float* lnb  = (const float*)d_in[12];
    float* out = (float*)d_out;

    const int SM4 = (64 * FLD + 256 * 128) * 4;        // 197632
    cudaFuncSetAttribute(k1_in_gemm,  cudaFuncAttributeMaxDynamicSharedMemorySize, K1_SMEM);
    cudaFuncSetAttribute(k4_out_gemm, cudaFuncAttributeMaxDynamicSharedMemorySize, SM4);

    dim3 g1(10, MM / 128);                             // (10, 1024)
    k1_in_gemm<<<g1, 256, K1_SMEM>>>(x, Win, bin, Wl, bl, Wg, bg);

    k2_hscan<<<MM / 256, 256>>>(thf, thr_);
    k3_wscan<<<MM / 256, 256>>>(thf, thr_);

    k4_out_gemm<<<MM / 64, 512, SM4>>>(Wout, bout, lnw, lnb, out);
}